// round 7
// baseline (speedup 1.0000x reference)
#include <cuda_runtime.h>
#include <cuda_bf16.h>
#include <math.h>
#include <stdint.h>

// ---------------- problem constants ----------------
#define Bn   4
#define Sd   4096
#define Dd   1024
#define Hh   8
#define Ff   4096          // EXP * D
#define Mtok 16384         // B * S
#define NCH  64            // scan chunks
#define CH   (Sd / NCH)    // 64 steps per chunk

// GEMM tiling: CTA 128x128x32, 4 warps of 64x64
#define BM 128
#define BN 128
#define BK 32
#define NTHR 128
#define STAGES 3
#define STAGE_BYTES 32768          // Ah 8K | Al 8K | Bh 8K | Bl 8K
#define OFF_AH 0
#define OFF_AL 8192
#define OFF_BH 16384
#define OFF_BL 24576
#define GEMM_SMEM (STAGES * STAGE_BYTES)   // 96 KB -> 2 CTAs/SM

// ---------------- small PTX helpers ------------------------------------------
__device__ __forceinline__ uint32_t smem_u32(const void* p) {
    uint32_t a;
    asm("{ .reg .u64 t; cvta.to.shared.u64 t, %1; cvt.u32.u64 %0, t; }"
        : "=r"(a) : "l"(p));
    return a;
}
#define CP_ASYNC16(dst, src) \
    asm volatile("cp.async.cg.shared.global [%0], [%1], 16;" \
        :: "r"(dst), "l"(src) : "memory")
#define CP_COMMIT() asm volatile("cp.async.commit_group;" ::: "memory")
#define CP_WAIT1()  asm volatile("cp.async.wait_group 1;" ::: "memory")

#define LDSM_X4(r0, r1, r2, r3, addr) \
    asm volatile("ldmatrix.sync.aligned.m8n8.x4.shared.b16 {%0,%1,%2,%3}, [%4];" \
        : "=r"(r0), "=r"(r1), "=r"(r2), "=r"(r3) : "r"(addr))

#define MMA_BF16(d, a, b) \
    asm volatile("mma.sync.aligned.m16n8k16.row.col.f32.bf16.bf16.f32 " \
        "{%0,%1,%2,%3}, {%4,%5,%6,%7}, {%8,%9}, {%0,%1,%2,%3};" \
        : "+f"((d)[0]), "+f"((d)[1]), "+f"((d)[2]), "+f"((d)[3]) \
        : "r"((a)[0]), "r"((a)[1]), "r"((a)[2]), "r"((a)[3]), \
          "r"((b)[0]), "r"((b)[1]))

// ---------------- scratch (device globals) ----------------------------------
__device__ __nv_bfloat16 g_hln_h [(size_t)Mtok * Dd];
__device__ __nv_bfloat16 g_hln_l [(size_t)Mtok * Dd];
__device__ __nv_bfloat16 g_act_h [(size_t)Mtok * Ff];
__device__ __nv_bfloat16 g_act_l [(size_t)Mtok * Ff];
__device__ float         g_x2    [(size_t)Mtok * Dd];
__device__ __nv_bfloat16 g_h2_h  [(size_t)Mtok * Dd];
__device__ __nv_bfloat16 g_h2_l  [(size_t)Mtok * Dd];
__device__ float         g_p     [(size_t)Mtok * Dd];
__device__ __nv_bfloat16 g_mx_h  [(size_t)Mtok * Dd];
__device__ __nv_bfloat16 g_mx_l  [(size_t)Mtok * Dd];
__device__ float         g_carry [(size_t)Bn * NCH * Dd];
__device__ __nv_bfloat16 g_w1_h  [(size_t)Ff * Dd];
__device__ __nv_bfloat16 g_w1_l  [(size_t)Ff * Dd];
__device__ __nv_bfloat16 g_w2_h  [(size_t)Dd * Ff];
__device__ __nv_bfloat16 g_w2_l  [(size_t)Dd * Ff];
__device__ __nv_bfloat16 g_pw_h  [(size_t)Dd * Dd];
__device__ __nv_bfloat16 g_pw_l  [(size_t)Dd * Dd];
__device__ __nv_bfloat16 g_ow_h  [(size_t)Dd * Dd];
__device__ __nv_bfloat16 g_ow_l  [(size_t)Dd * Dd];

// ---------------- fp32 -> bf16 hi/lo helpers ---------------------------------
__device__ __forceinline__ void split2(float x0, float x1, uint32_t& hi, uint32_t& lo) {
    __nv_bfloat16 h0 = __float2bfloat16(x0);
    __nv_bfloat16 h1 = __float2bfloat16(x1);
    __nv_bfloat16 l0 = __float2bfloat16(x0 - __bfloat162float(h0));
    __nv_bfloat16 l1 = __float2bfloat16(x1 - __bfloat162float(h1));
    __nv_bfloat162 hh; hh.x = h0; hh.y = h1;
    __nv_bfloat162 ll; ll.x = l0; ll.y = l1;
    hi = *(uint32_t*)&hh; lo = *(uint32_t*)&ll;
}

__global__ void __launch_bounds__(256) conv_hilo(
    const float* __restrict__ src, __nv_bfloat16* __restrict__ hi,
    __nv_bfloat16* __restrict__ lo, int n4)
{
    int i = blockIdx.x * 256 + threadIdx.x;
    if (i >= n4) return;
    float4 v = ((const float4*)src)[i];
    uint2 h, l;
    split2(v.x, v.y, h.x, l.x);
    split2(v.z, v.w, h.y, l.y);
    ((uint2*)hi)[i] = h;
    ((uint2*)lo)[i] = l;
}

// ---------------- LayerNorm -> bf16 hi/lo ------------------------------------
__global__ void __launch_bounds__(256) ln_bf16(
    const float* __restrict__ x, const float* __restrict__ g,
    const float* __restrict__ bet,
    __nv_bfloat16* __restrict__ ohi, __nv_bfloat16* __restrict__ olo)
{
    __shared__ float red[64];
    const long row = blockIdx.x;
    const int  t   = threadIdx.x;

    float4 v = ((const float4*)(x + row * Dd))[t];
    float s = v.x + v.y + v.z + v.w;
    float q = fmaf(v.x, v.x, fmaf(v.y, v.y, fmaf(v.z, v.z, v.w * v.w)));
    #pragma unroll
    for (int o = 16; o > 0; o >>= 1) {
        s += __shfl_xor_sync(0xffffffffu, s, o);
        q += __shfl_xor_sync(0xffffffffu, q, o);
    }
    if ((t & 31) == 0) { red[t >> 5] = s; red[32 + (t >> 5)] = q; }
    __syncthreads();
    if (t < 32) {
        s = (t < 8) ? red[t] : 0.f;
        q = (t < 8) ? red[32 + t] : 0.f;
        #pragma unroll
        for (int o = 4; o > 0; o >>= 1) {
            s += __shfl_xor_sync(0xffffffffu, s, o);
            q += __shfl_xor_sync(0xffffffffu, q, o);
        }
        if (t == 0) { red[0] = s; red[1] = q; }
    }
    __syncthreads();
    const float mean = red[0] * (1.f / Dd);
    const float var  = red[1] * (1.f / Dd) - mean * mean;
    const float rstd = rsqrtf(var + 1e-5f);
    float4 gg = ((const float4*)g)[t];
    float4 bb = ((const float4*)bet)[t];
    float o0 = (v.x - mean) * rstd * gg.x + bb.x;
    float o1 = (v.y - mean) * rstd * gg.y + bb.y;
    float o2 = (v.z - mean) * rstd * gg.z + bb.z;
    float o3 = (v.w - mean) * rstd * gg.w + bb.w;
    uint2 h, l;
    split2(o0, o1, h.x, l.x);
    split2(o2, o3, h.y, l.y);
    ((uint2*)(ohi + row * Dd))[t] = h;
    ((uint2*)(olo + row * Dd))[t] = l;
}

// ---------------- HMMA GEMM: C = (Ahi+Alo)(Whi+Wlo)^T + epilogue ------------
// EPI: 0 = +bias (fp32), 1 = silu(+bias) -> bf16 hi/lo, 2 = +bias+resid (fp32)

template<int K>
__device__ __forceinline__ void issue_stage(
    const __nv_bfloat16* __restrict__ aHi, const __nv_bfloat16* __restrict__ aLo,
    const __nv_bfloat16* __restrict__ wHi, const __nv_bfloat16* __restrict__ wLo,
    int kt, uint32_t stagebase, int tid)
{
    const int kofs = kt * BK;
    #pragma unroll
    for (int j = 0; j < 4; j++) {
        const int i = tid + j * NTHR;         // 0..511
        const int r = i >> 2;                 // row 0..127
        const int c = i & 3;                  // 16B-chunk 0..3
        const int sc = c ^ ((r >> 1) & 3);    // XOR swizzle
        const uint32_t d = stagebase + r * 64 + sc * 16;
        const size_t go = (size_t)r * K + kofs + c * 8;
        CP_ASYNC16(d + OFF_AH, aHi + go);
        CP_ASYNC16(d + OFF_AL, aLo + go);
        CP_ASYNC16(d + OFF_BH, wHi + go);
        CP_ASYNC16(d + OFF_BL, wLo + go);
    }
}

template<int N, int K, int EPI>
__global__ void __launch_bounds__(NTHR, 2) gemm_tc(
    const __nv_bfloat16* __restrict__ Ahi, const __nv_bfloat16* __restrict__ Alo,
    const __nv_bfloat16* __restrict__ Whi, const __nv_bfloat16* __restrict__ Wlo,
    const float* __restrict__ bias, const float* __restrict__ resid,
    float* __restrict__ Cf,
    __nv_bfloat16* __restrict__ Ohi, __nv_bfloat16* __restrict__ Olo)
{
    extern __shared__ char smem[];
    const uint32_t sb = smem_u32(smem);
    const int tid  = threadIdx.x;
    const int wid  = tid >> 5, lane = tid & 31;
    const int m0   = blockIdx.y * BM;
    const int n0   = blockIdx.x * BN;
    const int wm   = (wid & 1) * 64;      // warp M offset within tile
    const int wn   = (wid >> 1) * 64;     // warp N offset within tile

    const __nv_bfloat16* aHi = Ahi + (size_t)m0 * K;
    const __nv_bfloat16* aLo = Alo + (size_t)m0 * K;
    const __nv_bfloat16* wHi = Whi + (size_t)n0 * K;
    const __nv_bfloat16* wLo = Wlo + (size_t)n0 * K;

    constexpr int NK = K / BK;

    // prologue: fill STAGES-1 stages
    #pragma unroll
    for (int s = 0; s < STAGES - 1; s++) {
        issue_stage<K>(aHi, aLo, wHi, wLo, s, sb + s * STAGE_BYTES, tid);
        CP_COMMIT();
    }

    float acc[4][8][4];
    #pragma unroll
    for (int a = 0; a < 4; a++)
        #pragma unroll
        for (int b = 0; b < 8; b++)
            #pragma unroll
            for (int c = 0; c < 4; c++) acc[a][b][c] = 0.f;

    for (int kt = 0; kt < NK; kt++) {
        CP_WAIT1();
        __syncthreads();

        // issue next stage FIRST so loads overlap the MMAs below
        const int nxt = kt + STAGES - 1;
        if (nxt < NK)
            issue_stage<K>(aHi, aLo, wHi, wLo, nxt,
                           sb + (nxt % STAGES) * STAGE_BYTES, tid);
        CP_COMMIT();

        const uint32_t stg = sb + (kt % STAGES) * STAGE_BYTES;
        #pragma unroll
        for (int kc = 0; kc < 2; kc++) {
            const int halfk = lane >> 4;
            const int chunk = kc * 2 + halfk;
            const int lrow  = lane & 15;

            // A fragments (hi+lo), 4 M-frags of 16 rows
            uint32_t ah[4][4], al[4][4];
            #pragma unroll
            for (int mf = 0; mf < 4; mf++) {
                const int r = wm + mf * 16 + lrow;
                const int sc = chunk ^ ((r >> 1) & 3);
                const uint32_t ad = stg + r * 64 + sc * 16;
                LDSM_X4(ah[mf][0], ah[mf][1], ah[mf][2], ah[mf][3], ad + OFF_AH);
                LDSM_X4(al[mf][0], al[mf][1], al[mf][2], al[mf][3], ad + OFF_AL);
            }
            // ALL B fragments (hi+lo), 8 N-frags of 8 rows
            uint32_t bh[8][2], bl[8][2];
            #pragma unroll
            for (int p = 0; p < 4; p++) {
                const int r = wn + p * 16 + lrow;
                const int sc = chunk ^ ((r >> 1) & 3);
                const uint32_t bd = stg + r * 64 + sc * 16;
                uint32_t t0, t1, t2, t3;
                LDSM_X4(t0, t1, t2, t3, bd + OFF_BH);
                bh[2 * p][0] = t0; bh[2 * p + 1][0] = t1;
                bh[2 * p][1] = t2; bh[2 * p + 1][1] = t3;
                LDSM_X4(t0, t1, t2, t3, bd + OFF_BL);
                bl[2 * p][0] = t0; bl[2 * p + 1][0] = t1;
                bl[2 * p][1] = t2; bl[2 * p + 1][1] = t3;
            }

            // term-major schedule: 32 independent MMAs per term, so the
            // three RAW-dependent MMAs per accumulator are ~32 issues apart
            #pragma unroll
            for (int mf = 0; mf < 4; mf++)
                #pragma unroll
                for (int nf = 0; nf < 8; nf++)
                    MMA_BF16(acc[mf][nf], ah[mf], bh[nf]);
            #pragma unroll
            for (int mf = 0; mf < 4; mf++)
                #pragma unroll
                for (int nf = 0; nf < 8; nf++)
                    MMA_BF16(acc[mf][nf], ah[mf], bl[nf]);
            #pragma unroll
            for (int mf = 0; mf < 4; mf++)
                #pragma unroll
                for (int nf = 0; nf < 8; nf++)
                    MMA_BF16(acc[mf][nf], al[mf], bh[nf]);
        }
    }

    // ---------------- epilogue (register accumulators) ----------------
    #pragma unroll
    for (int nf = 0; nf < 8; nf++) {
        const int col = n0 + wn + nf * 8 + (lane & 3) * 2;
        const float b0 = bias[col], b1 = bias[col + 1];
        #pragma unroll
        for (int mf = 0; mf < 4; mf++) {
            const int r0 = m0 + wm + mf * 16 + (lane >> 2);
            #pragma unroll
            for (int hrow = 0; hrow < 2; hrow++) {
                const size_t row = (size_t)(r0 + hrow * 8);
                float v0 = acc[mf][nf][2 * hrow]     + b0;
                float v1 = acc[mf][nf][2 * hrow + 1] + b1;
                if (EPI == 1) {
                    v0 = v0 / (1.f + __expf(-v0));
                    v1 = v1 / (1.f + __expf(-v1));
                    uint32_t ph, pl;
                    split2(v0, v1, ph, pl);
                    *(uint32_t*)(Ohi + row * N + col) = ph;
                    *(uint32_t*)(Olo + row * N + col) = pl;
                } else {
                    if (EPI == 2) {
                        float2 rr = *(const float2*)(resid + row * N + col);
                        v0 += rr.x; v1 += rr.y;
                    }
                    float2 o = {v0, v1};
                    *(float2*)(Cf + row * N + col) = o;
                }
            }
        }
    }
}

// ---------------- decayed scan (3-pass chunked) ------------------------------
__device__ __forceinline__ float head_decay(const float* dr_ptr, int h) {
    float dr = dr_ptr[h];
    dr = fminf(fmaxf(dr, 0.9f), 1.0f);
    return powf(dr, 0.125f);
}

__global__ void __launch_bounds__(256) scan_pass1(
    const float* __restrict__ p, const float* __restrict__ mix_w,
    const float* __restrict__ decay_raw, float* __restrict__ carry)
{
    const int blk = blockIdx.x;
    const int b = blk / NCH, ch = blk % NCH;
    const int t = threadIdx.x;
    const int s0 = ch * CH;
    float cache[4] = {0.f, 0.f, 0.f, 0.f};
    float dly[4];
    #pragma unroll
    for (int j = 0; j < 4; j++) dly[j] = head_decay(decay_raw, (t + j * 256) >> 7);
    for (int s = s0; s < s0 + CH; s++) {
        const float* pr = p + ((long)b * Sd + s) * Dd;
        #pragma unroll
        for (int j = 0; j < 4; j++) {
            const int f = t + j * 256;
            const int h = f >> 7;
            const float c1 = (h < Hh / 2) ? 1.0f : mix_w[h * Sd + s];
            cache[j] = fmaf(dly[j], cache[j], pr[f] * c1);
        }
    }
    #pragma unroll
    for (int j = 0; j < 4; j++)
        carry[((long)b * NCH + ch) * Dd + t + j * 256] = cache[j];
}

__global__ void __launch_bounds__(256) scan_pass2(
    const float* __restrict__ decay_raw, float* __restrict__ carry)
{
    const int idx = blockIdx.x * 256 + threadIdx.x;
    const int b = idx >> 10, f = idx & 1023;
    const int h = f >> 7;
    float dr = fminf(fmaxf(decay_raw[h], 0.9f), 1.0f);
    float d2 = dr * dr, d4 = d2 * d2;
    const float dC = d4 * d4;   // dr^8 = decay^CH
    float cin = 0.f;
    for (int ch = 0; ch < NCH; ch++) {
        const long i = ((long)b * NCH + ch) * Dd + f;
        const float e = carry[i];
        carry[i] = cin;
        cin = fmaf(dC, cin, e);
    }
}

__global__ void __launch_bounds__(256) scan_pass3(
    const float* __restrict__ p, const float* __restrict__ mix_w,
    const float* __restrict__ mix_b, const float* __restrict__ decay_raw,
    const float* __restrict__ carry,
    __nv_bfloat16* __restrict__ mhi, __nv_bfloat16* __restrict__ mlo)
{
    const int blk = blockIdx.x;
    const int b = blk / NCH, ch = blk % NCH;
    const int t = threadIdx.x;
    const int s0 = ch * CH;
    float cache[4], dly[4];
    #pragma unroll
    for (int j = 0; j < 4; j++) {
        const int f = t + j * 256;
        dly[j]   = head_decay(decay_raw, f >> 7);
        cache[j] = carry[((long)b * NCH + ch) * Dd + f];
    }
    for (int s = s0; s < s0 + CH; s++) {
        const float* pr = p + ((long)b * Sd + s) * Dd;
        const long base = ((long)b * Sd + s) * Dd;
        #pragma unroll
        for (int j = 0; j < 4; j++) {
            const int f = t + j * 256;
            const int h = f >> 7;
            const float mw = mix_w[h * Sd + s];
            const float c1 = (h < Hh / 2) ? 1.0f : mw;
            const float c2 = (h < Hh / 2) ? mw : 1.0f;
            cache[j] = fmaf(dly[j], cache[j], pr[f] * c1);
            const float y = fmaf(c2, cache[j], mix_b[h * Sd + s]);
            __nv_bfloat16 hh = __float2bfloat16(y);
            mhi[base + f] = hh;
            mlo[base + f] = __float2bfloat16(y - __bfloat162float(hh));
        }
    }
}

// ---------------- launcher ----------------------------------------------------
extern "C" void kernel_launch(void* const* d_in, const int* in_sizes, int n_in,
                              void* d_out, int out_size)
{
    const float* x         = (const float*)d_in[0];
    const float* ln1_g     = (const float*)d_in[1];
    const float* ln1_b     = (const float*)d_in[2];
    const float* w1        = (const float*)d_in[3];
    const float* b1        = (const float*)d_in[4];
    const float* w2        = (const float*)d_in[5];
    const float* b2        = (const float*)d_in[6];
    const float* ln2_g     = (const float*)d_in[7];
    const float* ln2_b     = (const float*)d_in[8];
    const float* proj_w    = (const float*)d_in[9];
    const float* proj_b    = (const float*)d_in[10];
    const float* mix_w     = (const float*)d_in[11];
    const float* mix_b     = (const float*)d_in[12];
    const float* decay_raw = (const float*)d_in[13];
    const float* out_w     = (const float*)d_in[14];
    const float* out_b     = (const float*)d_in[15];
    float* out = (float*)d_out;

    __nv_bfloat16 *hlnh, *hlnl, *acth, *actl, *h2h, *h2l, *mxh, *mxl;
    __nv_bfloat16 *w1h, *w1l, *w2h, *w2l, *pwh, *pwl, *owh, *owl;
    float *x2, *pb, *carry;
    cudaGetSymbolAddress((void**)&hlnh, g_hln_h);
    cudaGetSymbolAddress((void**)&hlnl, g_hln_l);
    cudaGetSymbolAddress((void**)&acth, g_act_h);
    cudaGetSymbolAddress((void**)&actl, g_act_l);
    cudaGetSymbolAddress((void**)&x2,   g_x2);
    cudaGetSymbolAddress((void**)&h2h,  g_h2_h);
    cudaGetSymbolAddress((void**)&h2l,  g_h2_l);
    cudaGetSymbolAddress((void**)&pb,   g_p);
    cudaGetSymbolAddress((void**)&mxh,  g_mx_h);
    cudaGetSymbolAddress((void**)&mxl,  g_mx_l);
    cudaGetSymbolAddress((void**)&carry, g_carry);
    cudaGetSymbolAddress((void**)&w1h,  g_w1_h);
    cudaGetSymbolAddress((void**)&w1l,  g_w1_l);
    cudaGetSymbolAddress((void**)&w2h,  g_w2_h);
    cudaGetSymbolAddress((void**)&w2l,  g_w2_l);
    cudaGetSymbolAddress((void**)&pwh,  g_pw_h);
    cudaGetSymbolAddress((void**)&pwl,  g_pw_l);
    cudaGetSymbolAddress((void**)&owh,  g_ow_h);
    cudaGetSymbolAddress((void**)&owl,  g_ow_l);

    cudaFuncSetAttribute((const void*)gemm_tc<Ff, Dd, 1>,
                         cudaFuncAttributeMaxDynamicSharedMemorySize, GEMM_SMEM);
    cudaFuncSetAttribute((const void*)gemm_tc<Dd, Ff, 2>,
                         cudaFuncAttributeMaxDynamicSharedMemorySize, GEMM_SMEM);
    cudaFuncSetAttribute((const void*)gemm_tc<Dd, Dd, 0>,
                         cudaFuncAttributeMaxDynamicSharedMemorySize, GEMM_SMEM);
    cudaFuncSetAttribute((const void*)gemm_tc<Dd, Dd, 2>,
                         cudaFuncAttributeMaxDynamicSharedMemorySize, GEMM_SMEM);

    // 0) weight conversions fp32 -> bf16 hi/lo
    conv_hilo<<<(Ff * Dd / 4 + 255) / 256, 256>>>(w1, w1h, w1l, Ff * Dd / 4);
    conv_hilo<<<(Dd * Ff / 4 + 255) / 256, 256>>>(w2, w2h, w2l, Dd * Ff / 4);
    conv_hilo<<<(Dd * Dd / 4 + 255) / 256, 256>>>(proj_w, pwh, pwl, Dd * Dd / 4);
    conv_hilo<<<(Dd * Dd / 4 + 255) / 256, 256>>>(out_w, owh, owl, Dd * Dd / 4);

    // 1) LN1 -> bf16 hi/lo
    ln_bf16<<<Mtok, 256>>>(x, ln1_g, ln1_b, hlnh, hlnl);
    // 2) act = silu(hln @ w1^T + b1) -> bf16 hi/lo       [16384, 4096]
    gemm_tc<Ff, Dd, 1><<<dim3(Ff / BN, Mtok / BM), NTHR, GEMM_SMEM>>>(
        hlnh, hlnl, w1h, w1l, b1, nullptr, nullptr, acth, actl);
    // 3) x2 = act @ w2^T + b2 + x (fp32)                 [16384, 1024]
    gemm_tc<Dd, Ff, 2><<<dim3(Dd / BN, Mtok / BM), NTHR, GEMM_SMEM>>>(
        acth, actl, w2h, w2l, b2, x, x2, nullptr, nullptr);
    // 4) LN2 -> bf16 hi/lo
    ln_bf16<<<Mtok, 256>>>(x2, ln2_g, ln2_b, h2h, h2l);
    // 5) p = h2 @ proj_w^T + proj_b (fp32)               [16384, 1024]
    gemm_tc<Dd, Dd, 0><<<dim3(Dd / BN, Mtok / BM), NTHR, GEMM_SMEM>>>(
        h2h, h2l, pwh, pwl, proj_b, nullptr, pb, nullptr, nullptr);
    // 6-8) decayed scan over S (mixed -> bf16 hi/lo)
    scan_pass1<<<Bn * NCH, 256>>>(pb, mix_w, decay_raw, carry);
    scan_pass2<<<(Bn * Dd) / 256, 256>>>(decay_raw, carry);
    scan_pass3<<<Bn * NCH, 256>>>(pb, mix_w, mix_b, decay_raw, carry, mxh, mxl);
    // 9) out = mixed @ out_w^T + out_b + x2 (fp32)       [16384, 1024]
    gemm_tc<Dd, Dd, 2><<<dim3(Dd / BN, Mtok / BM), NTHR, GEMM_SMEM>>>(
        mxh, mxl, owh, owl, out_b, x2, out, nullptr, nullptr);
}

// round 8
// speedup vs baseline: 1.0155x; 1.0155x over previous
#include <cuda_runtime.h>
#include <cuda_bf16.h>
#include <math.h>
#include <stdint.h>

// ---------------- problem constants ----------------
#define Bn   4
#define Sd   4096
#define Dd   1024
#define Hh   8
#define Ff   4096          // EXP * D
#define Mtok 16384         // B * S
#define NCH  64            // scan chunks
#define CH   (Sd / NCH)    // 64 steps per chunk

// GEMM tiling: CTA 128x128x32, 8 warps of 64x32, 2 CTAs/SM (16 warps/SM)
#define BM 128
#define BN 128
#define BK 32
#define NTHR 256
#define STAGES 3
#define STAGE_BYTES 32768          // Ah 8K | Al 8K | Bh 8K | Bl 8K
#define OFF_AH 0
#define OFF_AL 8192
#define OFF_BH 16384
#define OFF_BL 24576
#define GEMM_SMEM (STAGES * STAGE_BYTES)   // 96 KB -> 2 CTAs/SM

// ---------------- small PTX helpers ------------------------------------------
__device__ __forceinline__ uint32_t smem_u32(const void* p) {
    uint32_t a;
    asm("{ .reg .u64 t; cvta.to.shared.u64 t, %1; cvt.u32.u64 %0, t; }"
        : "=r"(a) : "l"(p));
    return a;
}
#define CP_ASYNC16(dst, src) \
    asm volatile("cp.async.cg.shared.global [%0], [%1], 16;" \
        :: "r"(dst), "l"(src) : "memory")
#define CP_COMMIT() asm volatile("cp.async.commit_group;" ::: "memory")
#define CP_WAIT1()  asm volatile("cp.async.wait_group 1;" ::: "memory")

#define LDSM_X4(r0, r1, r2, r3, addr) \
    asm volatile("ldmatrix.sync.aligned.m8n8.x4.shared.b16 {%0,%1,%2,%3}, [%4];" \
        : "=r"(r0), "=r"(r1), "=r"(r2), "=r"(r3) : "r"(addr))

#define MMA_BF16(d, a, b) \
    asm volatile("mma.sync.aligned.m16n8k16.row.col.f32.bf16.bf16.f32 " \
        "{%0,%1,%2,%3}, {%4,%5,%6,%7}, {%8,%9}, {%0,%1,%2,%3};" \
        : "+f"((d)[0]), "+f"((d)[1]), "+f"((d)[2]), "+f"((d)[3]) \
        : "r"((a)[0]), "r"((a)[1]), "r"((a)[2]), "r"((a)[3]), \
          "r"((b)[0]), "r"((b)[1]))

// ---------------- scratch (device globals) ----------------------------------
__device__ __nv_bfloat16 g_hln_h [(size_t)Mtok * Dd];
__device__ __nv_bfloat16 g_hln_l [(size_t)Mtok * Dd];
__device__ __nv_bfloat16 g_act_h [(size_t)Mtok * Ff];
__device__ __nv_bfloat16 g_act_l [(size_t)Mtok * Ff];
__device__ float         g_x2    [(size_t)Mtok * Dd];
__device__ __nv_bfloat16 g_h2_h  [(size_t)Mtok * Dd];
__device__ __nv_bfloat16 g_h2_l  [(size_t)Mtok * Dd];
__device__ float         g_p     [(size_t)Mtok * Dd];
__device__ __nv_bfloat16 g_mx_h  [(size_t)Mtok * Dd];
__device__ __nv_bfloat16 g_mx_l  [(size_t)Mtok * Dd];
__device__ float         g_carry [(size_t)Bn * NCH * Dd];
__device__ __nv_bfloat16 g_w1_h  [(size_t)Ff * Dd];
__device__ __nv_bfloat16 g_w1_l  [(size_t)Ff * Dd];
__device__ __nv_bfloat16 g_w2_h  [(size_t)Dd * Ff];
__device__ __nv_bfloat16 g_w2_l  [(size_t)Dd * Ff];
__device__ __nv_bfloat16 g_pw_h  [(size_t)Dd * Dd];
__device__ __nv_bfloat16 g_pw_l  [(size_t)Dd * Dd];
__device__ __nv_bfloat16 g_ow_h  [(size_t)Dd * Dd];
__device__ __nv_bfloat16 g_ow_l  [(size_t)Dd * Dd];

// ---------------- fp32 -> bf16 hi/lo helpers ---------------------------------
__device__ __forceinline__ void split2(float x0, float x1, uint32_t& hi, uint32_t& lo) {
    __nv_bfloat16 h0 = __float2bfloat16(x0);
    __nv_bfloat16 h1 = __float2bfloat16(x1);
    __nv_bfloat16 l0 = __float2bfloat16(x0 - __bfloat162float(h0));
    __nv_bfloat16 l1 = __float2bfloat16(x1 - __bfloat162float(h1));
    __nv_bfloat162 hh; hh.x = h0; hh.y = h1;
    __nv_bfloat162 ll; ll.x = l0; ll.y = l1;
    hi = *(uint32_t*)&hh; lo = *(uint32_t*)&ll;
}

__global__ void __launch_bounds__(256) conv_hilo(
    const float* __restrict__ src, __nv_bfloat16* __restrict__ hi,
    __nv_bfloat16* __restrict__ lo, int n4)
{
    int i = blockIdx.x * 256 + threadIdx.x;
    if (i >= n4) return;
    float4 v = ((const float4*)src)[i];
    uint2 h, l;
    split2(v.x, v.y, h.x, l.x);
    split2(v.z, v.w, h.y, l.y);
    ((uint2*)hi)[i] = h;
    ((uint2*)lo)[i] = l;
}

// ---------------- LayerNorm -> bf16 hi/lo ------------------------------------
__global__ void __launch_bounds__(256) ln_bf16(
    const float* __restrict__ x, const float* __restrict__ g,
    const float* __restrict__ bet,
    __nv_bfloat16* __restrict__ ohi, __nv_bfloat16* __restrict__ olo)
{
    __shared__ float red[64];
    const long row = blockIdx.x;
    const int  t   = threadIdx.x;

    float4 v = ((const float4*)(x + row * Dd))[t];
    float s = v.x + v.y + v.z + v.w;
    float q = fmaf(v.x, v.x, fmaf(v.y, v.y, fmaf(v.z, v.z, v.w * v.w)));
    #pragma unroll
    for (int o = 16; o > 0; o >>= 1) {
        s += __shfl_xor_sync(0xffffffffu, s, o);
        q += __shfl_xor_sync(0xffffffffu, q, o);
    }
    if ((t & 31) == 0) { red[t >> 5] = s; red[32 + (t >> 5)] = q; }
    __syncthreads();
    if (t < 32) {
        s = (t < 8) ? red[t] : 0.f;
        q = (t < 8) ? red[32 + t] : 0.f;
        #pragma unroll
        for (int o = 4; o > 0; o >>= 1) {
            s += __shfl_xor_sync(0xffffffffu, s, o);
            q += __shfl_xor_sync(0xffffffffu, q, o);
        }
        if (t == 0) { red[0] = s; red[1] = q; }
    }
    __syncthreads();
    const float mean = red[0] * (1.f / Dd);
    const float var  = red[1] * (1.f / Dd) - mean * mean;
    const float rstd = rsqrtf(var + 1e-5f);
    float4 gg = ((const float4*)g)[t];
    float4 bb = ((const float4*)bet)[t];
    float o0 = (v.x - mean) * rstd * gg.x + bb.x;
    float o1 = (v.y - mean) * rstd * gg.y + bb.y;
    float o2 = (v.z - mean) * rstd * gg.z + bb.z;
    float o3 = (v.w - mean) * rstd * gg.w + bb.w;
    uint2 h, l;
    split2(o0, o1, h.x, l.x);
    split2(o2, o3, h.y, l.y);
    ((uint2*)(ohi + row * Dd))[t] = h;
    ((uint2*)(olo + row * Dd))[t] = l;
}

// ---------------- HMMA GEMM: C = (Ahi+Alo)(Whi+Wlo)^T + epilogue ------------
// EPI: 0 = +bias (fp32), 1 = silu(+bias) -> bf16 hi/lo, 2 = +bias+resid (fp32)

template<int K>
__device__ __forceinline__ void issue_stage(
    const __nv_bfloat16* __restrict__ aHi, const __nv_bfloat16* __restrict__ aLo,
    const __nv_bfloat16* __restrict__ wHi, const __nv_bfloat16* __restrict__ wLo,
    int kt, uint32_t stagebase, int tid)
{
    const int kofs = kt * BK;
    #pragma unroll
    for (int j = 0; j < 2; j++) {
        const int i = tid + j * NTHR;         // 0..511
        const int r = i >> 2;                 // row 0..127
        const int c = i & 3;                  // 16B-chunk 0..3
        const int sc = c ^ ((r >> 1) & 3);    // XOR swizzle
        const uint32_t d = stagebase + r * 64 + sc * 16;
        const size_t go = (size_t)r * K + kofs + c * 8;
        CP_ASYNC16(d + OFF_AH, aHi + go);
        CP_ASYNC16(d + OFF_AL, aLo + go);
        CP_ASYNC16(d + OFF_BH, wHi + go);
        CP_ASYNC16(d + OFF_BL, wLo + go);
    }
}

template<int N, int K, int EPI>
__global__ void __launch_bounds__(NTHR, 2) gemm_tc(
    const __nv_bfloat16* __restrict__ Ahi, const __nv_bfloat16* __restrict__ Alo,
    const __nv_bfloat16* __restrict__ Whi, const __nv_bfloat16* __restrict__ Wlo,
    const float* __restrict__ bias, const float* __restrict__ resid,
    float* __restrict__ Cf,
    __nv_bfloat16* __restrict__ Ohi, __nv_bfloat16* __restrict__ Olo)
{
    extern __shared__ char smem[];
    const uint32_t sb = smem_u32(smem);
    const int tid  = threadIdx.x;
    const int wid  = tid >> 5, lane = tid & 31;
    const int m0   = blockIdx.y * BM;
    const int n0   = blockIdx.x * BN;
    const int wm   = (wid & 1) * 64;      // warp M offset within tile
    const int wn   = (wid >> 1) * 32;     // warp N offset within tile

    const __nv_bfloat16* aHi = Ahi + (size_t)m0 * K;
    const __nv_bfloat16* aLo = Alo + (size_t)m0 * K;
    const __nv_bfloat16* wHi = Whi + (size_t)n0 * K;
    const __nv_bfloat16* wLo = Wlo + (size_t)n0 * K;

    constexpr int NK = K / BK;

    // prologue: fill STAGES-1 stages
    #pragma unroll
    for (int s = 0; s < STAGES - 1; s++) {
        issue_stage<K>(aHi, aLo, wHi, wLo, s, sb + s * STAGE_BYTES, tid);
        CP_COMMIT();
    }

    float acc[4][4][4];
    #pragma unroll
    for (int a = 0; a < 4; a++)
        #pragma unroll
        for (int b = 0; b < 4; b++)
            #pragma unroll
            for (int c = 0; c < 4; c++) acc[a][b][c] = 0.f;

    for (int kt = 0; kt < NK; kt++) {
        CP_WAIT1();
        __syncthreads();

        // issue next stage FIRST so loads overlap the MMAs below
        const int nxt = kt + STAGES - 1;
        if (nxt < NK)
            issue_stage<K>(aHi, aLo, wHi, wLo, nxt,
                           sb + (nxt % STAGES) * STAGE_BYTES, tid);
        CP_COMMIT();

        const uint32_t stg = sb + (kt % STAGES) * STAGE_BYTES;
        #pragma unroll
        for (int kc = 0; kc < 2; kc++) {
            const int halfk = lane >> 4;
            const int chunk = kc * 2 + halfk;
            const int lrow  = lane & 15;
            // A fragments (hi+lo), 4 M-frags of 16 rows
            uint32_t ah[4][4], al[4][4];
            #pragma unroll
            for (int mf = 0; mf < 4; mf++) {
                const int r = wm + mf * 16 + lrow;
                const int sc = chunk ^ ((r >> 1) & 3);
                const uint32_t ad = stg + r * 64 + sc * 16;
                LDSM_X4(ah[mf][0], ah[mf][1], ah[mf][2], ah[mf][3], ad + OFF_AH);
                LDSM_X4(al[mf][0], al[mf][1], al[mf][2], al[mf][3], ad + OFF_AL);
            }
            // B fragments loaded per 16-row pair (transient registers)
            #pragma unroll
            for (int p = 0; p < 2; p++) {
                const int r = wn + p * 16 + lrow;
                const int sc = chunk ^ ((r >> 1) & 3);
                const uint32_t bd = stg + r * 64 + sc * 16;
                uint32_t bh[2][2], bl[2][2];
                uint32_t t0, t1, t2, t3;
                LDSM_X4(t0, t1, t2, t3, bd + OFF_BH);
                bh[0][0] = t0; bh[1][0] = t1; bh[0][1] = t2; bh[1][1] = t3;
                LDSM_X4(t0, t1, t2, t3, bd + OFF_BL);
                bl[0][0] = t0; bl[1][0] = t1; bl[0][1] = t2; bl[1][1] = t3;
                #pragma unroll
                for (int mf = 0; mf < 4; mf++)
                    #pragma unroll
                    for (int q = 0; q < 2; q++) {
                        float* d = acc[mf][2 * p + q];
                        MMA_BF16(d, ah[mf], bh[q]);
                        MMA_BF16(d, ah[mf], bl[q]);
                        MMA_BF16(d, al[mf], bh[q]);
                    }
            }
        }
    }

    // ---------------- epilogue (register accumulators) ----------------
    #pragma unroll
    for (int nf = 0; nf < 4; nf++) {
        const int col = n0 + wn + nf * 8 + (lane & 3) * 2;
        const float b0 = bias[col], b1 = bias[col + 1];
        #pragma unroll
        for (int mf = 0; mf < 4; mf++) {
            const int r0 = m0 + wm + mf * 16 + (lane >> 2);
            #pragma unroll
            for (int hrow = 0; hrow < 2; hrow++) {
                const size_t row = (size_t)(r0 + hrow * 8);
                float v0 = acc[mf][nf][2 * hrow]     + b0;
                float v1 = acc[mf][nf][2 * hrow + 1] + b1;
                if (EPI == 1) {
                    v0 = v0 / (1.f + __expf(-v0));
                    v1 = v1 / (1.f + __expf(-v1));
                    uint32_t ph, pl;
                    split2(v0, v1, ph, pl);
                    *(uint32_t*)(Ohi + row * N + col) = ph;
                    *(uint32_t*)(Olo + row * N + col) = pl;
                } else {
                    if (EPI == 2) {
                        float2 rr = *(const float2*)(resid + row * N + col);
                        v0 += rr.x; v1 += rr.y;
                    }
                    float2 o = {v0, v1};
                    *(float2*)(Cf + row * N + col) = o;
                }
            }
        }
    }
}

// ---------------- decayed scan (3-pass chunked) ------------------------------
__device__ __forceinline__ float head_decay(const float* dr_ptr, int h) {
    float dr = dr_ptr[h];
    dr = fminf(fmaxf(dr, 0.9f), 1.0f);
    return powf(dr, 0.125f);
}

__global__ void __launch_bounds__(256) scan_pass1(
    const float* __restrict__ p, const float* __restrict__ mix_w,
    const float* __restrict__ decay_raw, float* __restrict__ carry)
{
    const int blk = blockIdx.x;
    const int b = blk / NCH, ch = blk % NCH;
    const int t = threadIdx.x;
    const int s0 = ch * CH;
    float cache[4] = {0.f, 0.f, 0.f, 0.f};
    float dly[4];
    #pragma unroll
    for (int j = 0; j < 4; j++) dly[j] = head_decay(decay_raw, (t + j * 256) >> 7);
    for (int s = s0; s < s0 + CH; s++) {
        const float* pr = p + ((long)b * Sd + s) * Dd;
        #pragma unroll
        for (int j = 0; j < 4; j++) {
            const int f = t + j * 256;
            const int h = f >> 7;
            const float c1 = (h < Hh / 2) ? 1.0f : mix_w[h * Sd + s];
            cache[j] = fmaf(dly[j], cache[j], pr[f] * c1);
        }
    }
    #pragma unroll
    for (int j = 0; j < 4; j++)
        carry[((long)b * NCH + ch) * Dd + t + j * 256] = cache[j];
}

__global__ void __launch_bounds__(256) scan_pass2(
    const float* __restrict__ decay_raw, float* __restrict__ carry)
{
    const int idx = blockIdx.x * 256 + threadIdx.x;
    const int b = idx >> 10, f = idx & 1023;
    const int h = f >> 7;
    float dr = fminf(fmaxf(decay_raw[h], 0.9f), 1.0f);
    float d2 = dr * dr, d4 = d2 * d2;
    const float dC = d4 * d4;   // dr^8 = decay^CH
    float cin = 0.f;
    for (int ch = 0; ch < NCH; ch++) {
        const long i = ((long)b * NCH + ch) * Dd + f;
        const float e = carry[i];
        carry[i] = cin;
        cin = fmaf(dC, cin, e);
    }
}

__global__ void __launch_bounds__(256) scan_pass3(
    const float* __restrict__ p, const float* __restrict__ mix_w,
    const float* __restrict__ mix_b, const float* __restrict__ decay_raw,
    const float* __restrict__ carry,
    __nv_bfloat16* __restrict__ mhi, __nv_bfloat16* __restrict__ mlo)
{
    const int blk = blockIdx.x;
    const int b = blk / NCH, ch = blk % NCH;
    const int t = threadIdx.x;
    const int s0 = ch * CH;
    float cache[4], dly[4];
    #pragma unroll
    for (int j = 0; j < 4; j++) {
        const int f = t + j * 256;
        dly[j]   = head_decay(decay_raw, f >> 7);
        cache[j] = carry[((long)b * NCH + ch) * Dd + f];
    }
    for (int s = s0; s < s0 + CH; s++) {
        const float* pr = p + ((long)b * Sd + s) * Dd;
        const long base = ((long)b * Sd + s) * Dd;
        #pragma unroll
        for (int j = 0; j < 4; j++) {
            const int f = t + j * 256;
            const int h = f >> 7;
            const float mw = mix_w[h * Sd + s];
            const float c1 = (h < Hh / 2) ? 1.0f : mw;
            const float c2 = (h < Hh / 2) ? mw : 1.0f;
            cache[j] = fmaf(dly[j], cache[j], pr[f] * c1);
            const float y = fmaf(c2, cache[j], mix_b[h * Sd + s]);
            __nv_bfloat16 hh = __float2bfloat16(y);
            mhi[base + f] = hh;
            mlo[base + f] = __float2bfloat16(y - __bfloat162float(hh));
        }
    }
}

// ---------------- launcher ----------------------------------------------------
extern "C" void kernel_launch(void* const* d_in, const int* in_sizes, int n_in,
                              void* d_out, int out_size)
{
    const float* x         = (const float*)d_in[0];
    const float* ln1_g     = (const float*)d_in[1];
    const float* ln1_b     = (const float*)d_in[2];
    const float* w1        = (const float*)d_in[3];
    const float* b1        = (const float*)d_in[4];
    const float* w2        = (const float*)d_in[5];
    const float* b2        = (const float*)d_in[6];
    const float* ln2_g     = (const float*)d_in[7];
    const float* ln2_b     = (const float*)d_in[8];
    const float* proj_w    = (const float*)d_in[9];
    const float* proj_b    = (const float*)d_in[10];
    const float* mix_w     = (const float*)d_in[11];
    const float* mix_b     = (const float*)d_in[12];
    const float* decay_raw = (const float*)d_in[13];
    const float* out_w     = (const float*)d_in[14];
    const float* out_b     = (const float*)d_in[15];
    float* out = (float*)d_out;

    __nv_bfloat16 *hlnh, *hlnl, *acth, *actl, *h2h, *h2l, *mxh, *mxl;
    __nv_bfloat16 *w1h, *w1l, *w2h, *w2l, *pwh, *pwl, *owh, *owl;
    float *x2, *pb, *carry;
    cudaGetSymbolAddress((void**)&hlnh, g_hln_h);
    cudaGetSymbolAddress((void**)&hlnl, g_hln_l);
    cudaGetSymbolAddress((void**)&acth, g_act_h);
    cudaGetSymbolAddress((void**)&actl, g_act_l);
    cudaGetSymbolAddress((void**)&x2,   g_x2);
    cudaGetSymbolAddress((void**)&h2h,  g_h2_h);
    cudaGetSymbolAddress((void**)&h2l,  g_h2_l);
    cudaGetSymbolAddress((void**)&pb,   g_p);
    cudaGetSymbolAddress((void**)&mxh,  g_mx_h);
    cudaGetSymbolAddress((void**)&mxl,  g_mx_l);
    cudaGetSymbolAddress((void**)&carry, g_carry);
    cudaGetSymbolAddress((void**)&w1h,  g_w1_h);
    cudaGetSymbolAddress((void**)&w1l,  g_w1_l);
    cudaGetSymbolAddress((void**)&w2h,  g_w2_h);
    cudaGetSymbolAddress((void**)&w2l,  g_w2_l);
    cudaGetSymbolAddress((void**)&pwh,  g_pw_h);
    cudaGetSymbolAddress((void**)&pwl,  g_pw_l);
    cudaGetSymbolAddress((void**)&owh,  g_ow_h);
    cudaGetSymbolAddress((void**)&owl,  g_ow_l);

    cudaFuncSetAttribute((const void*)gemm_tc<Ff, Dd, 1>,
                         cudaFuncAttributeMaxDynamicSharedMemorySize, GEMM_SMEM);
    cudaFuncSetAttribute((const void*)gemm_tc<Dd, Ff, 2>,
                         cudaFuncAttributeMaxDynamicSharedMemorySize, GEMM_SMEM);
    cudaFuncSetAttribute((const void*)gemm_tc<Dd, Dd, 0>,
                         cudaFuncAttributeMaxDynamicSharedMemorySize, GEMM_SMEM);
    cudaFuncSetAttribute((const void*)gemm_tc<Dd, Dd, 2>,
                         cudaFuncAttributeMaxDynamicSharedMemorySize, GEMM_SMEM);

    // 0) weight conversions fp32 -> bf16 hi/lo
    conv_hilo<<<(Ff * Dd / 4 + 255) / 256, 256>>>(w1, w1h, w1l, Ff * Dd / 4);
    conv_hilo<<<(Dd * Ff / 4 + 255) / 256, 256>>>(w2, w2h, w2l, Dd * Ff / 4);
    conv_hilo<<<(Dd * Dd / 4 + 255) / 256, 256>>>(proj_w, pwh, pwl, Dd * Dd / 4);
    conv_hilo<<<(Dd * Dd / 4 + 255) / 256, 256>>>(out_w, owh, owl, Dd * Dd / 4);

    // 1) LN1 -> bf16 hi/lo
    ln_bf16<<<Mtok, 256>>>(x, ln1_g, ln1_b, hlnh, hlnl);
    // 2) act = silu(hln @ w1^T + b1) -> bf16 hi/lo       [16384, 4096]
    gemm_tc<Ff, Dd, 1><<<dim3(Ff / BN, Mtok / BM), NTHR, GEMM_SMEM>>>(
        hlnh, hlnl, w1h, w1l, b1, nullptr, nullptr, acth, actl);
    // 3) x2 = act @ w2^T + b2 + x (fp32)                 [16384, 1024]
    gemm_tc<Dd, Ff, 2><<<dim3(Dd / BN, Mtok / BM), NTHR, GEMM_SMEM>>>(
        acth, actl, w2h, w2l, b2, x, x2, nullptr, nullptr);
    // 4) LN2 -> bf16 hi/lo
    ln_bf16<<<Mtok, 256>>>(x2, ln2_g, ln2_b, h2h, h2l);
    // 5) p = h2 @ proj_w^T + proj_b (fp32)               [16384, 1024]
    gemm_tc<Dd, Dd, 0><<<dim3(Dd / BN, Mtok / BM), NTHR, GEMM_SMEM>>>(
        h2h, h2l, pwh, pwl, proj_b, nullptr, pb, nullptr, nullptr);
    // 6-8) decayed scan over S (mixed -> bf16 hi/lo)
    scan_pass1<<<Bn * NCH, 256>>>(pb, mix_w, decay_raw, carry);
    scan_pass2<<<(Bn * Dd) / 256, 256>>>(decay_raw, carry);
    scan_pass3<<<Bn * NCH, 256>>>(pb, mix_w, mix_b, decay_raw, carry, mxh, mxl);
    // 9) out = mixed @ out_w^T + out_b + x2 (fp32)       [16384, 1024]
    gemm_tc<Dd, Dd, 2><<<dim3(Dd / BN, Mtok / BM), NTHR, GEMM_SMEM>>>(
        mxh, mxl, owh, owl, out_b, x2, out, nullptr, nullptr);
}

// round 9
// speedup vs baseline: 2.5117x; 2.4734x over previous
#include <cuda_runtime.h>
#include <cuda_fp16.h>
#include <math.h>
#include <stdint.h>

// ---------------- problem constants ----------------
#define Bn   4
#define Sd   4096
#define Dd   1024
#define Hh   8
#define Ff   4096          // EXP * D
#define Mtok 16384         // B * S
#define NCH  64            // scan chunks
#define CH   (Sd / NCH)    // 64 steps per chunk

// GEMM tiling: CTA 128x128x32, 8 warps of 64x32, 2 CTAs/SM
#define BM 128
#define BN 128
#define BK 32
#define NTHR 256
#define STAGES 4
#define STAGE_BYTES 16384          // A 8K | B 8K (fp16)
#define OFF_A 0
#define OFF_B 8192
#define GEMM_SMEM (STAGES * STAGE_BYTES)   // 64 KB -> 2 CTAs/SM

// ---------------- small PTX helpers ------------------------------------------
__device__ __forceinline__ uint32_t smem_u32(const void* p) {
    uint32_t a;
    asm("{ .reg .u64 t; cvta.to.shared.u64 t, %1; cvt.u32.u64 %0, t; }"
        : "=r"(a) : "l"(p));
    return a;
}
#define CP_ASYNC16(dst, src) \
    asm volatile("cp.async.cg.shared.global [%0], [%1], 16;" \
        :: "r"(dst), "l"(src) : "memory")
#define CP_COMMIT() asm volatile("cp.async.commit_group;" ::: "memory")
#define CP_WAIT2()  asm volatile("cp.async.wait_group 2;" ::: "memory")

#define LDSM_X4(r0, r1, r2, r3, addr) \
    asm volatile("ldmatrix.sync.aligned.m8n8.x4.shared.b16 {%0,%1,%2,%3}, [%4];" \
        : "=r"(r0), "=r"(r1), "=r"(r2), "=r"(r3) : "r"(addr))

#define MMA_F16(d, a, b) \
    asm volatile("mma.sync.aligned.m16n8k16.row.col.f32.f16.f16.f32 " \
        "{%0,%1,%2,%3}, {%4,%5,%6,%7}, {%8,%9}, {%0,%1,%2,%3};" \
        : "+f"((d)[0]), "+f"((d)[1]), "+f"((d)[2]), "+f"((d)[3]) \
        : "r"((a)[0]), "r"((a)[1]), "r"((a)[2]), "r"((a)[3]), \
          "r"((b)[0]), "r"((b)[1]))

// ---------------- scratch (device globals) ----------------------------------
__device__ __half g_hln [(size_t)Mtok * Dd];
__device__ __half g_act [(size_t)Mtok * Ff];
__device__ float  g_x2  [(size_t)Mtok * Dd];
__device__ __half g_h2  [(size_t)Mtok * Dd];
__device__ float  g_p   [(size_t)Mtok * Dd];
__device__ __half g_mx  [(size_t)Mtok * Dd];
__device__ float  g_carry[(size_t)Bn * NCH * Dd];
__device__ __half g_w1  [(size_t)Ff * Dd];
__device__ __half g_w2  [(size_t)Dd * Ff];
__device__ __half g_pw  [(size_t)Dd * Dd];
__device__ __half g_ow  [(size_t)Dd * Dd];

// ---------------- fp32 -> fp16 conversion ------------------------------------
__global__ void __launch_bounds__(256) conv_h(
    const float* __restrict__ src, __half* __restrict__ dst, int n4)
{
    int i = blockIdx.x * 256 + threadIdx.x;
    if (i >= n4) return;
    float4 v = ((const float4*)src)[i];
    __half2 a = __floats2half2_rn(v.x, v.y);
    __half2 b = __floats2half2_rn(v.z, v.w);
    uint2 o;
    o.x = *(uint32_t*)&a;
    o.y = *(uint32_t*)&b;
    ((uint2*)dst)[i] = o;
}

// ---------------- LayerNorm -> fp16 -------------------------------------------
__global__ void __launch_bounds__(256) ln_f16(
    const float* __restrict__ x, const float* __restrict__ g,
    const float* __restrict__ bet, __half* __restrict__ o16)
{
    __shared__ float red[64];
    const long row = blockIdx.x;
    const int  t   = threadIdx.x;

    float4 v = ((const float4*)(x + row * Dd))[t];
    float s = v.x + v.y + v.z + v.w;
    float q = fmaf(v.x, v.x, fmaf(v.y, v.y, fmaf(v.z, v.z, v.w * v.w)));
    #pragma unroll
    for (int o = 16; o > 0; o >>= 1) {
        s += __shfl_xor_sync(0xffffffffu, s, o);
        q += __shfl_xor_sync(0xffffffffu, q, o);
    }
    if ((t & 31) == 0) { red[t >> 5] = s; red[32 + (t >> 5)] = q; }
    __syncthreads();
    if (t < 32) {
        s = (t < 8) ? red[t] : 0.f;
        q = (t < 8) ? red[32 + t] : 0.f;
        #pragma unroll
        for (int o = 4; o > 0; o >>= 1) {
            s += __shfl_xor_sync(0xffffffffu, s, o);
            q += __shfl_xor_sync(0xffffffffu, q, o);
        }
        if (t == 0) { red[0] = s; red[1] = q; }
    }
    __syncthreads();
    const float mean = red[0] * (1.f / Dd);
    const float var  = red[1] * (1.f / Dd) - mean * mean;
    const float rstd = rsqrtf(var + 1e-5f);
    float4 gg = ((const float4*)g)[t];
    float4 bb = ((const float4*)bet)[t];
    float o0 = (v.x - mean) * rstd * gg.x + bb.x;
    float o1 = (v.y - mean) * rstd * gg.y + bb.y;
    float o2 = (v.z - mean) * rstd * gg.z + bb.z;
    float o3 = (v.w - mean) * rstd * gg.w + bb.w;
    __half2 h0 = __floats2half2_rn(o0, o1);
    __half2 h1 = __floats2half2_rn(o2, o3);
    uint2 o;
    o.x = *(uint32_t*)&h0;
    o.y = *(uint32_t*)&h1;
    ((uint2*)(o16 + row * Dd))[t] = o;
}

// ---------------- fp16 HMMA GEMM: C = A W^T + epilogue ------------------------
// EPI: 0 = +bias (fp32), 1 = silu(+bias) -> fp16, 2 = +bias+resid (fp32)

template<int K>
__device__ __forceinline__ void issue_stage(
    const __half* __restrict__ A, const __half* __restrict__ W,
    int kt, uint32_t stagebase, int tid)
{
    const int kofs = kt * BK;
    #pragma unroll
    for (int j = 0; j < 2; j++) {
        const int i = tid + j * NTHR;         // 0..511
        const int r = i >> 2;                 // row 0..127
        const int c = i & 3;                  // 16B-chunk 0..3
        const int sc = c ^ ((r >> 1) & 3);    // XOR swizzle
        const uint32_t d = stagebase + r * 64 + sc * 16;
        const size_t go = (size_t)r * K + kofs + c * 8;
        CP_ASYNC16(d + OFF_A, A + go);
        CP_ASYNC16(d + OFF_B, W + go);
    }
}

template<int N, int K, int EPI>
__global__ void __launch_bounds__(NTHR, 2) gemm_tc(
    const __half* __restrict__ Ah, const __half* __restrict__ Wh,
    const float* __restrict__ bias, const float* __restrict__ resid,
    float* __restrict__ Cf, __half* __restrict__ Oh)
{
    extern __shared__ char smem[];
    const uint32_t sb = smem_u32(smem);
    const int tid  = threadIdx.x;
    const int wid  = tid >> 5, lane = tid & 31;
    const int m0   = blockIdx.y * BM;
    const int n0   = blockIdx.x * BN;
    const int wm   = (wid & 1) * 64;      // warp M offset within tile
    const int wn   = (wid >> 1) * 32;     // warp N offset within tile

    const __half* A = Ah + (size_t)m0 * K;
    const __half* W = Wh + (size_t)n0 * K;

    constexpr int NK = K / BK;

    // prologue: fill STAGES-1 stages
    #pragma unroll
    for (int s = 0; s < STAGES - 1; s++) {
        issue_stage<K>(A, W, s, sb + s * STAGE_BYTES, tid);
        CP_COMMIT();
    }

    float acc[4][4][4];
    #pragma unroll
    for (int a = 0; a < 4; a++)
        #pragma unroll
        for (int b = 0; b < 4; b++)
            #pragma unroll
            for (int c = 0; c < 4; c++) acc[a][b][c] = 0.f;

    for (int kt = 0; kt < NK; kt++) {
        CP_WAIT2();
        __syncthreads();

        // issue next stage FIRST so loads overlap the MMAs below
        const int nxt = kt + STAGES - 1;
        if (nxt < NK)
            issue_stage<K>(A, W, nxt, sb + (nxt % STAGES) * STAGE_BYTES, tid);
        CP_COMMIT();

        const uint32_t stg = sb + (kt % STAGES) * STAGE_BYTES;
        #pragma unroll
        for (int kc = 0; kc < 2; kc++) {
            const int halfk = lane >> 4;
            const int chunk = kc * 2 + halfk;
            const int lrow  = lane & 15;
            // A fragments, 4 M-frags of 16 rows
            uint32_t af[4][4];
            #pragma unroll
            for (int mf = 0; mf < 4; mf++) {
                const int r = wm + mf * 16 + lrow;
                const int sc = chunk ^ ((r >> 1) & 3);
                const uint32_t ad = stg + r * 64 + sc * 16;
                LDSM_X4(af[mf][0], af[mf][1], af[mf][2], af[mf][3], ad + OFF_A);
            }
            // B fragments, 4 N-frags of 8 rows (loaded per 16-row pair)
            #pragma unroll
            for (int p = 0; p < 2; p++) {
                const int r = wn + p * 16 + lrow;
                const int sc = chunk ^ ((r >> 1) & 3);
                const uint32_t bd = stg + r * 64 + sc * 16;
                uint32_t bf[2][2];
                uint32_t t0, t1, t2, t3;
                LDSM_X4(t0, t1, t2, t3, bd + OFF_B);
                bf[0][0] = t0; bf[1][0] = t1; bf[0][1] = t2; bf[1][1] = t3;
                #pragma unroll
                for (int mf = 0; mf < 4; mf++)
                    #pragma unroll
                    for (int q = 0; q < 2; q++)
                        MMA_F16(acc[mf][2 * p + q], af[mf], bf[q]);
            }
        }
    }

    // ---------------- epilogue (register accumulators) ----------------
    #pragma unroll
    for (int nf = 0; nf < 4; nf++) {
        const int col = n0 + wn + nf * 8 + (lane & 3) * 2;
        const float b0 = bias[col], b1 = bias[col + 1];
        #pragma unroll
        for (int mf = 0; mf < 4; mf++) {
            const int r0 = m0 + wm + mf * 16 + (lane >> 2);
            #pragma unroll
            for (int hrow = 0; hrow < 2; hrow++) {
                const size_t row = (size_t)(r0 + hrow * 8);
                float v0 = acc[mf][nf][2 * hrow]     + b0;
                float v1 = acc[mf][nf][2 * hrow + 1] + b1;
                if (EPI == 1) {
                    v0 = v0 / (1.f + __expf(-v0));
                    v1 = v1 / (1.f + __expf(-v1));
                    __half2 hv = __floats2half2_rn(v0, v1);
                    *(uint32_t*)(Oh + row * N + col) = *(uint32_t*)&hv;
                } else {
                    if (EPI == 2) {
                        float2 rr = *(const float2*)(resid + row * N + col);
                        v0 += rr.x; v1 += rr.y;
                    }
                    float2 o = {v0, v1};
                    *(float2*)(Cf + row * N + col) = o;
                }
            }
        }
    }
}

// ---------------- decayed scan (3-pass chunked) ------------------------------
__device__ __forceinline__ float head_decay(const float* dr_ptr, int h) {
    float dr = dr_ptr[h];
    dr = fminf(fmaxf(dr, 0.9f), 1.0f);
    return powf(dr, 0.125f);
}

__global__ void __launch_bounds__(256) scan_pass1(
    const float* __restrict__ p, const float* __restrict__ mix_w,
    const float* __restrict__ decay_raw, float* __restrict__ carry)
{
    const int blk = blockIdx.x;
    const int b = blk / NCH, ch = blk % NCH;
    const int t = threadIdx.x;
    const int s0 = ch * CH;
    float cache[4] = {0.f, 0.f, 0.f, 0.f};
    float dly[4];
    #pragma unroll
    for (int j = 0; j < 4; j++) dly[j] = head_decay(decay_raw, (t + j * 256) >> 7);
    for (int s = s0; s < s0 + CH; s++) {
        const float* pr = p + ((long)b * Sd + s) * Dd;
        #pragma unroll
        for (int j = 0; j < 4; j++) {
            const int f = t + j * 256;
            const int h = f >> 7;
            const float c1 = (h < Hh / 2) ? 1.0f : mix_w[h * Sd + s];
            cache[j] = fmaf(dly[j], cache[j], pr[f] * c1);
        }
    }
    #pragma unroll
    for (int j = 0; j < 4; j++)
        carry[((long)b * NCH + ch) * Dd + t + j * 256] = cache[j];
}

__global__ void __launch_bounds__(256) scan_pass2(
    const float* __restrict__ decay_raw, float* __restrict__ carry)
{
    const int idx = blockIdx.x * 256 + threadIdx.x;
    const int b = idx >> 10, f = idx & 1023;
    const int h = f >> 7;
    float dr = fminf(fmaxf(decay_raw[h], 0.9f), 1.0f);
    float d2 = dr * dr, d4 = d2 * d2;
    const float dC = d4 * d4;   // dr^8 = decay^CH
    float cin = 0.f;
    for (int ch = 0; ch < NCH; ch++) {
        const long i = ((long)b * NCH + ch) * Dd + f;
        const float e = carry[i];
        carry[i] = cin;
        cin = fmaf(dC, cin, e);
    }
}

__global__ void __launch_bounds__(256) scan_pass3(
    const float* __restrict__ p, const float* __restrict__ mix_w,
    const float* __restrict__ mix_b, const float* __restrict__ decay_raw,
    const float* __restrict__ carry, __half* __restrict__ mx)
{
    const int blk = blockIdx.x;
    const int b = blk / NCH, ch = blk % NCH;
    const int t = threadIdx.x;
    const int s0 = ch * CH;
    float cache[4], dly[4];
    #pragma unroll
    for (int j = 0; j < 4; j++) {
        const int f = t + j * 256;
        dly[j]   = head_decay(decay_raw, f >> 7);
        cache[j] = carry[((long)b * NCH + ch) * Dd + f];
    }
    for (int s = s0; s < s0 + CH; s++) {
        const float* pr = p + ((long)b * Sd + s) * Dd;
        const long base = ((long)b * Sd + s) * Dd;
        #pragma unroll
        for (int j = 0; j < 4; j++) {
            const int f = t + j * 256;
            const int h = f >> 7;
            const float mw = mix_w[h * Sd + s];
            const float c1 = (h < Hh / 2) ? 1.0f : mw;
            const float c2 = (h < Hh / 2) ? mw : 1.0f;
            cache[j] = fmaf(dly[j], cache[j], pr[f] * c1);
            const float y = fmaf(c2, cache[j], mix_b[h * Sd + s]);
            mx[base + f] = __float2half_rn(y);
        }
    }
}

// ---------------- launcher ----------------------------------------------------
extern "C" void kernel_launch(void* const* d_in, const int* in_sizes, int n_in,
                              void* d_out, int out_size)
{
    const float* x         = (const float*)d_in[0];
    const float* ln1_g     = (const float*)d_in[1];
    const float* ln1_b     = (const float*)d_in[2];
    const float* w1        = (const float*)d_in[3];
    const float* b1        = (const float*)d_in[4];
    const float* w2        = (const float*)d_in[5];
    const float* b2        = (const float*)d_in[6];
    const float* ln2_g     = (const float*)d_in[7];
    const float* ln2_b     = (const float*)d_in[8];
    const float* proj_w    = (const float*)d_in[9];
    const float* proj_b    = (const float*)d_in[10];
    const float* mix_w     = (const float*)d_in[11];
    const float* mix_b     = (const float*)d_in[12];
    const float* decay_raw = (const float*)d_in[13];
    const float* out_w     = (const float*)d_in[14];
    const float* out_b     = (const float*)d_in[15];
    float* out = (float*)d_out;

    __half *hln, *act, *h2, *mx, *w1h, *w2h, *pwh, *owh;
    float *x2, *pb, *carry;
    cudaGetSymbolAddress((void**)&hln,  g_hln);
    cudaGetSymbolAddress((void**)&act,  g_act);
    cudaGetSymbolAddress((void**)&x2,   g_x2);
    cudaGetSymbolAddress((void**)&h2,   g_h2);
    cudaGetSymbolAddress((void**)&pb,   g_p);
    cudaGetSymbolAddress((void**)&mx,   g_mx);
    cudaGetSymbolAddress((void**)&carry, g_carry);
    cudaGetSymbolAddress((void**)&w1h,  g_w1);
    cudaGetSymbolAddress((void**)&w2h,  g_w2);
    cudaGetSymbolAddress((void**)&pwh,  g_pw);
    cudaGetSymbolAddress((void**)&owh,  g_ow);

    cudaFuncSetAttribute((const void*)gemm_tc<Ff, Dd, 1>,
                         cudaFuncAttributeMaxDynamicSharedMemorySize, GEMM_SMEM);
    cudaFuncSetAttribute((const void*)gemm_tc<Dd, Ff, 2>,
                         cudaFuncAttributeMaxDynamicSharedMemorySize, GEMM_SMEM);
    cudaFuncSetAttribute((const void*)gemm_tc<Dd, Dd, 0>,
                         cudaFuncAttributeMaxDynamicSharedMemorySize, GEMM_SMEM);
    cudaFuncSetAttribute((const void*)gemm_tc<Dd, Dd, 2>,
                         cudaFuncAttributeMaxDynamicSharedMemorySize, GEMM_SMEM);

    // 0) weight conversions fp32 -> fp16
    conv_h<<<(Ff * Dd / 4 + 255) / 256, 256>>>(w1, w1h, Ff * Dd / 4);
    conv_h<<<(Dd * Ff / 4 + 255) / 256, 256>>>(w2, w2h, Dd * Ff / 4);
    conv_h<<<(Dd * Dd / 4 + 255) / 256, 256>>>(proj_w, pwh, Dd * Dd / 4);
    conv_h<<<(Dd * Dd / 4 + 255) / 256, 256>>>(out_w, owh, Dd * Dd / 4);

    // 1) LN1 -> fp16
    ln_f16<<<Mtok, 256>>>(x, ln1_g, ln1_b, hln);
    // 2) act = silu(hln @ w1^T + b1) -> fp16             [16384, 4096]
    gemm_tc<Ff, Dd, 1><<<dim3(Ff / BN, Mtok / BM), NTHR, GEMM_SMEM>>>(
        hln, w1h, b1, nullptr, nullptr, act);
    // 3) x2 = act @ w2^T + b2 + x (fp32)                 [16384, 1024]
    gemm_tc<Dd, Ff, 2><<<dim3(Dd / BN, Mtok / BM), NTHR, GEMM_SMEM>>>(
        act, w2h, b2, x, x2, nullptr);
    // 4) LN2 -> fp16
    ln_f16<<<Mtok, 256>>>(x2, ln2_g, ln2_b, h2);
    // 5) p = h2 @ proj_w^T + proj_b (fp32)               [16384, 1024]
    gemm_tc<Dd, Dd, 0><<<dim3(Dd / BN, Mtok / BM), NTHR, GEMM_SMEM>>>(
        h2, pwh, proj_b, nullptr, pb, nullptr);
    // 6-8) decayed scan over S (mixed -> fp16)
    scan_pass1<<<Bn * NCH, 256>>>(pb, mix_w, decay_raw, carry);
    scan_pass2<<<(Bn * Dd) / 256, 256>>>(decay_raw, carry);
    scan_pass3<<<Bn * NCH, 256>>>(pb, mix_w, mix_b, decay_raw, carry, mx);
    // 9) out = mixed @ out_w^T + out_b + x2 (fp32)       [16384, 1024]
    gemm_tc<Dd, Dd, 2><<<dim3(Dd / BN, Mtok / BM), NTHR, GEMM_SMEM>>>(
        mx, owh, out_b, x2, out, nullptr);
}

// round 10
// speedup vs baseline: 2.6253x; 1.0452x over previous
#include <cuda_runtime.h>
#include <cuda_fp16.h>
#include <math.h>
#include <stdint.h>

// ---------------- problem constants ----------------
#define Bn   4
#define Sd   4096
#define Dd   1024
#define Hh   8
#define Ff   4096          // EXP * D
#define Mtok 16384         // B * S
#define NCH  64            // scan chunks
#define CH   (Sd / NCH)    // 64 steps per chunk

// GEMM tiling: CTA 128x128x64, 8 warps of 64x32, 2 CTAs/SM
#define BM 128
#define BN 128
#define BK 64
#define NTHR 256
#define STAGES 3
#define STAGE_BYTES 32768          // A 16K | B 16K (fp16, 128B rows)
#define OFF_A 0
#define OFF_B 16384
#define GEMM_SMEM (STAGES * STAGE_BYTES)   // 96 KB -> 2 CTAs/SM

// ---------------- small PTX helpers ------------------------------------------
__device__ __forceinline__ uint32_t smem_u32(const void* p) {
    uint32_t a;
    asm("{ .reg .u64 t; cvta.to.shared.u64 t, %1; cvt.u32.u64 %0, t; }"
        : "=r"(a) : "l"(p));
    return a;
}
#define CP_ASYNC16(dst, src) \
    asm volatile("cp.async.cg.shared.global [%0], [%1], 16;" \
        :: "r"(dst), "l"(src) : "memory")
#define CP_COMMIT() asm volatile("cp.async.commit_group;" ::: "memory")
#define CP_WAIT1()  asm volatile("cp.async.wait_group 1;" ::: "memory")

#define LDSM_X4(r0, r1, r2, r3, addr) \
    asm volatile("ldmatrix.sync.aligned.m8n8.x4.shared.b16 {%0,%1,%2,%3}, [%4];" \
        : "=r"(r0), "=r"(r1), "=r"(r2), "=r"(r3) : "r"(addr))

#define MMA_F16(d, a, b) \
    asm volatile("mma.sync.aligned.m16n8k16.row.col.f32.f16.f16.f32 " \
        "{%0,%1,%2,%3}, {%4,%5,%6,%7}, {%8,%9}, {%0,%1,%2,%3};" \
        : "+f"((d)[0]), "+f"((d)[1]), "+f"((d)[2]), "+f"((d)[3]) \
        : "r"((a)[0]), "r"((a)[1]), "r"((a)[2]), "r"((a)[3]), \
          "r"((b)[0]), "r"((b)[1]))

// ---------------- scratch (device globals) ----------------------------------
__device__ __half g_hln [(size_t)Mtok * Dd];
__device__ __half g_act [(size_t)Mtok * Ff];
__device__ float  g_x2  [(size_t)Mtok * Dd];
__device__ __half g_h2  [(size_t)Mtok * Dd];
__device__ float  g_p   [(size_t)Mtok * Dd];
__device__ __half g_mx  [(size_t)Mtok * Dd];
__device__ float  g_carry[(size_t)Bn * NCH * Dd];
__device__ __half g_w1  [(size_t)Ff * Dd];
__device__ __half g_w2  [(size_t)Dd * Ff];
__device__ __half g_pw  [(size_t)Dd * Dd];
__device__ __half g_ow  [(size_t)Dd * Dd];

// ---------------- fp32 -> fp16 conversion ------------------------------------
__global__ void __launch_bounds__(256) conv_h(
    const float* __restrict__ src, __half* __restrict__ dst, int n4)
{
    int i = blockIdx.x * 256 + threadIdx.x;
    if (i >= n4) return;
    float4 v = ((const float4*)src)[i];
    __half2 a = __floats2half2_rn(v.x, v.y);
    __half2 b = __floats2half2_rn(v.z, v.w);
    uint2 o;
    o.x = *(uint32_t*)&a;
    o.y = *(uint32_t*)&b;
    ((uint2*)dst)[i] = o;
}

// ---------------- LayerNorm -> fp16 -------------------------------------------
__global__ void __launch_bounds__(256) ln_f16(
    const float* __restrict__ x, const float* __restrict__ g,
    const float* __restrict__ bet, __half* __restrict__ o16)
{
    __shared__ float red[64];
    const long row = blockIdx.x;
    const int  t   = threadIdx.x;

    float4 v = ((const float4*)(x + row * Dd))[t];
    float s = v.x + v.y + v.z + v.w;
    float q = fmaf(v.x, v.x, fmaf(v.y, v.y, fmaf(v.z, v.z, v.w * v.w)));
    #pragma unroll
    for (int o = 16; o > 0; o >>= 1) {
        s += __shfl_xor_sync(0xffffffffu, s, o);
        q += __shfl_xor_sync(0xffffffffu, q, o);
    }
    if ((t & 31) == 0) { red[t >> 5] = s; red[32 + (t >> 5)] = q; }
    __syncthreads();
    if (t < 32) {
        s = (t < 8) ? red[t] : 0.f;
        q = (t < 8) ? red[32 + t] : 0.f;
        #pragma unroll
        for (int o = 4; o > 0; o >>= 1) {
            s += __shfl_xor_sync(0xffffffffu, s, o);
            q += __shfl_xor_sync(0xffffffffu, q, o);
        }
        if (t == 0) { red[0] = s; red[1] = q; }
    }
    __syncthreads();
    const float mean = red[0] * (1.f / Dd);
    const float var  = red[1] * (1.f / Dd) - mean * mean;
    const float rstd = rsqrtf(var + 1e-5f);
    float4 gg = ((const float4*)g)[t];
    float4 bb = ((const float4*)bet)[t];
    float o0 = (v.x - mean) * rstd * gg.x + bb.x;
    float o1 = (v.y - mean) * rstd * gg.y + bb.y;
    float o2 = (v.z - mean) * rstd * gg.z + bb.z;
    float o3 = (v.w - mean) * rstd * gg.w + bb.w;
    __half2 h0 = __floats2half2_rn(o0, o1);
    __half2 h1 = __floats2half2_rn(o2, o3);
    uint2 o;
    o.x = *(uint32_t*)&h0;
    o.y = *(uint32_t*)&h1;
    ((uint2*)(o16 + row * Dd))[t] = o;
}

// ---------------- fp16 HMMA GEMM: C = A W^T + epilogue ------------------------
// EPI: 0 = +bias (fp32), 1 = silu(+bias) -> fp16, 2 = +bias+resid (fp32)
// SMEM rows are 128 B wide (64 fp16); swizzle: chunk c ^= (row & 7)

template<int K>
__device__ __forceinline__ void issue_stage(
    const __half* __restrict__ A, const __half* __restrict__ W,
    int kt, uint32_t stagebase, int tid)
{
    const int kofs = kt * BK;
    #pragma unroll
    for (int j = 0; j < 4; j++) {
        const int i = tid + j * NTHR;         // 0..1023
        const int r = i >> 3;                 // row 0..127
        const int c = i & 7;                  // 16B-chunk 0..7
        const int sc = c ^ (r & 7);           // XOR swizzle (128B rows)
        const uint32_t d = stagebase + r * 128 + sc * 16;
        const size_t go = (size_t)r * K + kofs + c * 8;
        CP_ASYNC16(d + OFF_A, A + go);
        CP_ASYNC16(d + OFF_B, W + go);
    }
}

template<int N, int K, int EPI>
__global__ void __launch_bounds__(NTHR, 2) gemm_tc(
    const __half* __restrict__ Ah, const __half* __restrict__ Wh,
    const float* __restrict__ bias, const float* __restrict__ resid,
    float* __restrict__ Cf, __half* __restrict__ Oh)
{
    extern __shared__ char smem[];
    const uint32_t sb = smem_u32(smem);
    const int tid  = threadIdx.x;
    const int wid  = tid >> 5, lane = tid & 31;
    const int m0   = blockIdx.y * BM;
    const int n0   = blockIdx.x * BN;
    const int wm   = (wid & 1) * 64;      // warp M offset within tile
    const int wn   = (wid >> 1) * 32;     // warp N offset within tile

    const __half* A = Ah + (size_t)m0 * K;
    const __half* W = Wh + (size_t)n0 * K;

    constexpr int NK = K / BK;

    // prologue: fill STAGES-1 stages
    #pragma unroll
    for (int s = 0; s < STAGES - 1; s++) {
        issue_stage<K>(A, W, s, sb + s * STAGE_BYTES, tid);
        CP_COMMIT();
    }

    float acc[4][4][4];
    #pragma unroll
    for (int a = 0; a < 4; a++)
        #pragma unroll
        for (int b = 0; b < 4; b++)
            #pragma unroll
            for (int c = 0; c < 4; c++) acc[a][b][c] = 0.f;

    for (int kt = 0; kt < NK; kt++) {
        CP_WAIT1();
        __syncthreads();

        // issue next stage FIRST so loads overlap the MMAs below
        const int nxt = kt + STAGES - 1;
        if (nxt < NK)
            issue_stage<K>(A, W, nxt, sb + (nxt % STAGES) * STAGE_BYTES, tid);
        CP_COMMIT();

        const uint32_t stg = sb + (kt % STAGES) * STAGE_BYTES;
        #pragma unroll
        for (int kc = 0; kc < 4; kc++) {
            const int halfk = lane >> 4;
            const int chunk = kc * 2 + halfk;     // 16B chunk 0..7
            const int lrow  = lane & 15;
            // A fragments, 4 M-frags of 16 rows
            uint32_t af[4][4];
            #pragma unroll
            for (int mf = 0; mf < 4; mf++) {
                const int r = wm + mf * 16 + lrow;
                const int sc = chunk ^ (r & 7);
                const uint32_t ad = stg + r * 128 + sc * 16;
                LDSM_X4(af[mf][0], af[mf][1], af[mf][2], af[mf][3], ad + OFF_A);
            }
            // B fragments, 4 N-frags of 8 rows (loaded per 16-row pair)
            #pragma unroll
            for (int p = 0; p < 2; p++) {
                const int r = wn + p * 16 + lrow;
                const int sc = chunk ^ (r & 7);
                const uint32_t bd = stg + r * 128 + sc * 16;
                uint32_t bf[2][2];
                uint32_t t0, t1, t2, t3;
                LDSM_X4(t0, t1, t2, t3, bd + OFF_B);
                bf[0][0] = t0; bf[1][0] = t1; bf[0][1] = t2; bf[1][1] = t3;
                #pragma unroll
                for (int mf = 0; mf < 4; mf++)
                    #pragma unroll
                    for (int q = 0; q < 2; q++)
                        MMA_F16(acc[mf][2 * p + q], af[mf], bf[q]);
            }
        }
    }

    // ---------------- epilogue (register accumulators) ----------------
    #pragma unroll
    for (int nf = 0; nf < 4; nf++) {
        const int col = n0 + wn + nf * 8 + (lane & 3) * 2;
        const float b0 = bias[col], b1 = bias[col + 1];
        #pragma unroll
        for (int mf = 0; mf < 4; mf++) {
            const int r0 = m0 + wm + mf * 16 + (lane >> 2);
            #pragma unroll
            for (int hrow = 0; hrow < 2; hrow++) {
                const size_t row = (size_t)(r0 + hrow * 8);
                float v0 = acc[mf][nf][2 * hrow]     + b0;
                float v1 = acc[mf][nf][2 * hrow + 1] + b1;
                if (EPI == 1) {
                    v0 = v0 / (1.f + __expf(-v0));
                    v1 = v1 / (1.f + __expf(-v1));
                    __half2 hv = __floats2half2_rn(v0, v1);
                    *(uint32_t*)(Oh + row * N + col) = *(uint32_t*)&hv;
                } else {
                    if (EPI == 2) {
                        float2 rr = *(const float2*)(resid + row * N + col);
                        v0 += rr.x; v1 += rr.y;
                    }
                    float2 o = {v0, v1};
                    *(float2*)(Cf + row * N + col) = o;
                }
            }
        }
    }
}

// ---------------- decayed scan (3-pass chunked) ------------------------------
__device__ __forceinline__ float head_decay(const float* dr_ptr, int h) {
    float dr = dr_ptr[h];
    dr = fminf(fmaxf(dr, 0.9f), 1.0f);
    return powf(dr, 0.125f);
}

__global__ void __launch_bounds__(256) scan_pass1(
    const float* __restrict__ p, const float* __restrict__ mix_w,
    const float* __restrict__ decay_raw, float* __restrict__ carry)
{
    const int blk = blockIdx.x;
    const int b = blk / NCH, ch = blk % NCH;
    const int t = threadIdx.x;
    const int s0 = ch * CH;
    float cache[4] = {0.f, 0.f, 0.f, 0.f};
    float dly[4];
    #pragma unroll
    for (int j = 0; j < 4; j++) dly[j] = head_decay(decay_raw, (t + j * 256) >> 7);
    for (int s = s0; s < s0 + CH; s++) {
        const float* pr = p + ((long)b * Sd + s) * Dd;
        #pragma unroll
        for (int j = 0; j < 4; j++) {
            const int f = t + j * 256;
            const int h = f >> 7;
            const float c1 = (h < Hh / 2) ? 1.0f : mix_w[h * Sd + s];
            cache[j] = fmaf(dly[j], cache[j], pr[f] * c1);
        }
    }
    #pragma unroll
    for (int j = 0; j < 4; j++)
        carry[((long)b * NCH + ch) * Dd + t + j * 256] = cache[j];
}

__global__ void __launch_bounds__(256) scan_pass2(
    const float* __restrict__ decay_raw, float* __restrict__ carry)
{
    const int idx = blockIdx.x * 256 + threadIdx.x;
    const int b = idx >> 10, f = idx & 1023;
    const int h = f >> 7;
    float dr = fminf(fmaxf(decay_raw[h], 0.9f), 1.0f);
    float d2 = dr * dr, d4 = d2 * d2;
    const float dC = d4 * d4;   // dr^8 = decay^CH
    float cin = 0.f;
    for (int ch = 0; ch < NCH; ch++) {
        const long i = ((long)b * NCH + ch) * Dd + f;
        const float e = carry[i];
        carry[i] = cin;
        cin = fmaf(dC, cin, e);
    }
}

__global__ void __launch_bounds__(256) scan_pass3(
    const float* __restrict__ p, const float* __restrict__ mix_w,
    const float* __restrict__ mix_b, const float* __restrict__ decay_raw,
    const float* __restrict__ carry, __half* __restrict__ mx)
{
    const int blk = blockIdx.x;
    const int b = blk / NCH, ch = blk % NCH;
    const int t = threadIdx.x;
    const int s0 = ch * CH;
    float cache[4], dly[4];
    #pragma unroll
    for (int j = 0; j < 4; j++) {
        const int f = t + j * 256;
        dly[j]   = head_decay(decay_raw, f >> 7);
        cache[j] = carry[((long)b * NCH + ch) * Dd + f];
    }
    for (int s = s0; s < s0 + CH; s++) {
        const float* pr = p + ((long)b * Sd + s) * Dd;
        const long base = ((long)b * Sd + s) * Dd;
        #pragma unroll
        for (int j = 0; j < 4; j++) {
            const int f = t + j * 256;
            const int h = f >> 7;
            const float mw = mix_w[h * Sd + s];
            const float c1 = (h < Hh / 2) ? 1.0f : mw;
            const float c2 = (h < Hh / 2) ? mw : 1.0f;
            cache[j] = fmaf(dly[j], cache[j], pr[f] * c1);
            const float y = fmaf(c2, cache[j], mix_b[h * Sd + s]);
            mx[base + f] = __float2half_rn(y);
        }
    }
}

// ---------------- launcher ----------------------------------------------------
extern "C" void kernel_launch(void* const* d_in, const int* in_sizes, int n_in,
                              void* d_out, int out_size)
{
    const float* x         = (const float*)d_in[0];
    const float* ln1_g     = (const float*)d_in[1];
    const float* ln1_b     = (const float*)d_in[2];
    const float* w1        = (const float*)d_in[3];
    const float* b1        = (const float*)d_in[4];
    const float* w2        = (const float*)d_in[5];
    const float* b2        = (const float*)d_in[6];
    const float* ln2_g     = (const float*)d_in[7];
    const float* ln2_b     = (const float*)d_in[8];
    const float* proj_w    = (const float*)d_in[9];
    const float* proj_b    = (const float*)d_in[10];
    const float* mix_w     = (const float*)d_in[11];
    const float* mix_b     = (const float*)d_in[12];
    const float* decay_raw = (const float*)d_in[13];
    const float* out_w     = (const float*)d_in[14];
    const float* out_b     = (const float*)d_in[15];
    float* out = (float*)d_out;

    __half *hln, *act, *h2, *mx, *w1h, *w2h, *pwh, *owh;
    float *x2, *pb, *carry;
    cudaGetSymbolAddress((void**)&hln,  g_hln);
    cudaGetSymbolAddress((void**)&act,  g_act);
    cudaGetSymbolAddress((void**)&x2,   g_x2);
    cudaGetSymbolAddress((void**)&h2,   g_h2);
    cudaGetSymbolAddress((void**)&pb,   g_p);
    cudaGetSymbolAddress((void**)&mx,   g_mx);
    cudaGetSymbolAddress((void**)&carry, g_carry);
    cudaGetSymbolAddress((void**)&w1h,  g_w1);
    cudaGetSymbolAddress((void**)&w2h,  g_w2);
    cudaGetSymbolAddress((void**)&pwh,  g_pw);
    cudaGetSymbolAddress((void**)&owh,  g_ow);

    cudaFuncSetAttribute((const void*)gemm_tc<Ff, Dd, 1>,
                         cudaFuncAttributeMaxDynamicSharedMemorySize, GEMM_SMEM);
    cudaFuncSetAttribute((const void*)gemm_tc<Dd, Ff, 2>,
                         cudaFuncAttributeMaxDynamicSharedMemorySize, GEMM_SMEM);
    cudaFuncSetAttribute((const void*)gemm_tc<Dd, Dd, 0>,
                         cudaFuncAttributeMaxDynamicSharedMemorySize, GEMM_SMEM);
    cudaFuncSetAttribute((const void*)gemm_tc<Dd, Dd, 2>,
                         cudaFuncAttributeMaxDynamicSharedMemorySize, GEMM_SMEM);

    // 0) weight conversions fp32 -> fp16
    conv_h<<<(Ff * Dd / 4 + 255) / 256, 256>>>(w1, w1h, Ff * Dd / 4);
    conv_h<<<(Dd * Ff / 4 + 255) / 256, 256>>>(w2, w2h, Dd * Ff / 4);
    conv_h<<<(Dd * Dd / 4 + 255) / 256, 256>>>(proj_w, pwh, Dd * Dd / 4);
    conv_h<<<(Dd * Dd / 4 + 255) / 256, 256>>>(out_w, owh, Dd * Dd / 4);

    // 1) LN1 -> fp16
    ln_f16<<<Mtok, 256>>>(x, ln1_g, ln1_b, hln);
    // 2) act = silu(hln @ w1^T + b1) -> fp16             [16384, 4096]
    gemm_tc<Ff, Dd, 1><<<dim3(Ff / BN, Mtok / BM), NTHR, GEMM_SMEM>>>(
        hln, w1h, b1, nullptr, nullptr, act);
    // 3) x2 = act @ w2^T + b2 + x (fp32)                 [16384, 1024]
    gemm_tc<Dd, Ff, 2><<<dim3(Dd / BN, Mtok / BM), NTHR, GEMM_SMEM>>>(
        act, w2h, b2, x, x2, nullptr);
    // 4) LN2 -> fp16
    ln_f16<<<Mtok, 256>>>(x2, ln2_g, ln2_b, h2);
    // 5) p = h2 @ proj_w^T + proj_b (fp32)               [16384, 1024]
    gemm_tc<Dd, Dd, 0><<<dim3(Dd / BN, Mtok / BM), NTHR, GEMM_SMEM>>>(
        h2, pwh, proj_b, nullptr, pb, nullptr);
    // 6-8) decayed scan over S (mixed -> fp16)
    scan_pass1<<<Bn * NCH, 256>>>(pb, mix_w, decay_raw, carry);
    scan_pass2<<<(Bn * Dd) / 256, 256>>>(decay_raw, carry);
    scan_pass3<<<Bn * NCH, 256>>>(pb, mix_w, mix_b, decay_raw, carry, mx);
    // 9) out = mixed @ out_w^T + out_b + x2 (fp32)       [16384, 1024]
    gemm_tc<Dd, Dd, 2><<<dim3(Dd / BN, Mtok / BM), NTHR, GEMM_SMEM>>>(
        mx, owh, out_b, x2, out, nullptr);
}

// round 11
// speedup vs baseline: 2.8142x; 1.0720x over previous
#include <cuda_runtime.h>
#include <cuda_fp16.h>
#include <math.h>
#include <stdint.h>

// ---------------- problem constants ----------------
#define Bn   4
#define Sd   4096
#define Dd   1024
#define Hh   8
#define Ff   4096          // EXP * D
#define Mtok 16384         // B * S
#define NCH  64            // scan chunks
#define CH   (Sd / NCH)    // 64 steps per chunk

// GEMM tiling: CTA 128x128x64, 8 warps of 64x32, 2 CTAs/SM
#define BM 128
#define BN 128
#define BK 64
#define NTHR 256
#define STAGES 3
#define STAGE_BYTES 32768          // A 16K | B 16K (fp16, 128B rows)
#define OFF_A 0
#define OFF_B 16384
#define GEMM_SMEM (STAGES * STAGE_BYTES)   // 96 KB -> 2 CTAs/SM

// ---------------- small PTX helpers ------------------------------------------
__device__ __forceinline__ uint32_t smem_u32(const void* p) {
    uint32_t a;
    asm("{ .reg .u64 t; cvta.to.shared.u64 t, %1; cvt.u32.u64 %0, t; }"
        : "=r"(a) : "l"(p));
    return a;
}
#define CP_ASYNC16(dst, src) \
    asm volatile("cp.async.cg.shared.global [%0], [%1], 16;" \
        :: "r"(dst), "l"(src) : "memory")
#define CP_COMMIT() asm volatile("cp.async.commit_group;" ::: "memory")
#define CP_WAIT1()  asm volatile("cp.async.wait_group 1;" ::: "memory")

#define LDSM_X4(r0, r1, r2, r3, addr) \
    asm volatile("ldmatrix.sync.aligned.m8n8.x4.shared.b16 {%0,%1,%2,%3}, [%4];" \
        : "=r"(r0), "=r"(r1), "=r"(r2), "=r"(r3) : "r"(addr))

#define MMA_F16(d, a, b) \
    asm volatile("mma.sync.aligned.m16n8k16.row.col.f32.f16.f16.f32 " \
        "{%0,%1,%2,%3}, {%4,%5,%6,%7}, {%8,%9}, {%0,%1,%2,%3};" \
        : "+f"((d)[0]), "+f"((d)[1]), "+f"((d)[2]), "+f"((d)[3]) \
        : "r"((a)[0]), "r"((a)[1]), "r"((a)[2]), "r"((a)[3]), \
          "r"((b)[0]), "r"((b)[1]))

// ---------------- scratch (device globals) ----------------------------------
__device__ __half g_hln [(size_t)Mtok * Dd];
__device__ __half g_act [(size_t)Mtok * Ff];
__device__ float  g_x2  [(size_t)Mtok * Dd];
__device__ __half g_h2  [(size_t)Mtok * Dd];
__device__ __half g_p   [(size_t)Mtok * Dd];
__device__ __half g_mx  [(size_t)Mtok * Dd];
__device__ float  g_carry[(size_t)Bn * NCH * Dd];
__device__ __half g_w1  [(size_t)Ff * Dd];
__device__ __half g_w2  [(size_t)Dd * Ff];
__device__ __half g_pw  [(size_t)Dd * Dd];
__device__ __half g_ow  [(size_t)Dd * Dd];

// ---------------- fp32 -> fp16 conversion ------------------------------------
__global__ void __launch_bounds__(256) conv_h(
    const float* __restrict__ src, __half* __restrict__ dst, int n4)
{
    int i = blockIdx.x * 256 + threadIdx.x;
    if (i >= n4) return;
    float4 v = ((const float4*)src)[i];
    __half2 a = __floats2half2_rn(v.x, v.y);
    __half2 b = __floats2half2_rn(v.z, v.w);
    uint2 o;
    o.x = *(uint32_t*)&a;
    o.y = *(uint32_t*)&b;
    ((uint2*)dst)[i] = o;
}

// ---------------- LayerNorm -> fp16, warp per row ------------------------------
__global__ void __launch_bounds__(256) ln_f16(
    const float* __restrict__ x, const float* __restrict__ g,
    const float* __restrict__ bet, __half* __restrict__ o16)
{
    const int wid  = threadIdx.x >> 5;
    const int lane = threadIdx.x & 31;
    const long row = (long)blockIdx.x * 8 + wid;

    const float4* xr = (const float4*)(x + row * Dd);
    float4 v[8];
    #pragma unroll
    for (int i = 0; i < 8; i++) v[i] = xr[lane + i * 32];

    float s = 0.f, q = 0.f;
    #pragma unroll
    for (int i = 0; i < 8; i++) {
        s += v[i].x + v[i].y + v[i].z + v[i].w;
        q = fmaf(v[i].x, v[i].x, q);
        q = fmaf(v[i].y, v[i].y, q);
        q = fmaf(v[i].z, v[i].z, q);
        q = fmaf(v[i].w, v[i].w, q);
    }
    #pragma unroll
    for (int o = 16; o > 0; o >>= 1) {
        s += __shfl_xor_sync(0xffffffffu, s, o);
        q += __shfl_xor_sync(0xffffffffu, q, o);
    }
    const float mean = s * (1.f / Dd);
    const float var  = q * (1.f / Dd) - mean * mean;
    const float rstd = rsqrtf(var + 1e-5f);

    uint2* outp = (uint2*)(o16 + row * Dd);
    #pragma unroll
    for (int i = 0; i < 8; i++) {
        float4 gg = ((const float4*)g)[lane + i * 32];
        float4 bb = ((const float4*)bet)[lane + i * 32];
        float o0 = (v[i].x - mean) * rstd * gg.x + bb.x;
        float o1 = (v[i].y - mean) * rstd * gg.y + bb.y;
        float o2 = (v[i].z - mean) * rstd * gg.z + bb.z;
        float o3 = (v[i].w - mean) * rstd * gg.w + bb.w;
        __half2 h0 = __floats2half2_rn(o0, o1);
        __half2 h1 = __floats2half2_rn(o2, o3);
        uint2 o;
        o.x = *(uint32_t*)&h0;
        o.y = *(uint32_t*)&h1;
        outp[lane + i * 32] = o;
    }
}

// ---------------- fp16 HMMA GEMM: C = A W^T + epilogue ------------------------
// EPI: 0 = +bias -> fp16, 1 = silu(+bias) -> fp16, 2 = +bias+resid -> fp32
// SMEM rows are 128 B wide (64 fp16); swizzle: chunk c ^= (row & 7)

template<int K>
__device__ __forceinline__ void issue_stage(
    const __half* __restrict__ A, const __half* __restrict__ W,
    int kt, uint32_t stagebase, int tid)
{
    const int kofs = kt * BK;
    #pragma unroll
    for (int j = 0; j < 4; j++) {
        const int i = tid + j * NTHR;         // 0..1023
        const int r = i >> 3;                 // row 0..127
        const int c = i & 7;                  // 16B-chunk 0..7
        const int sc = c ^ (r & 7);           // XOR swizzle (128B rows)
        const uint32_t d = stagebase + r * 128 + sc * 16;
        const size_t go = (size_t)r * K + kofs + c * 8;
        CP_ASYNC16(d + OFF_A, A + go);
        CP_ASYNC16(d + OFF_B, W + go);
    }
}

template<int N, int K, int EPI>
__global__ void __launch_bounds__(NTHR, 2) gemm_tc(
    const __half* __restrict__ Ah, const __half* __restrict__ Wh,
    const float* __restrict__ bias, const float* __restrict__ resid,
    float* __restrict__ Cf, __half* __restrict__ Oh)
{
    extern __shared__ char smem[];
    const uint32_t sb = smem_u32(smem);
    const int tid  = threadIdx.x;
    const int wid  = tid >> 5, lane = tid & 31;
    const int m0   = blockIdx.y * BM;
    const int n0   = blockIdx.x * BN;
    const int wm   = (wid & 1) * 64;      // warp M offset within tile
    const int wn   = (wid >> 1) * 32;     // warp N offset within tile

    const __half* A = Ah + (size_t)m0 * K;
    const __half* W = Wh + (size_t)n0 * K;

    constexpr int NK = K / BK;

    // prologue: fill STAGES-1 stages
    #pragma unroll
    for (int s = 0; s < STAGES - 1; s++) {
        issue_stage<K>(A, W, s, sb + s * STAGE_BYTES, tid);
        CP_COMMIT();
    }

    float acc[4][4][4];
    #pragma unroll
    for (int a = 0; a < 4; a++)
        #pragma unroll
        for (int b = 0; b < 4; b++)
            #pragma unroll
            for (int c = 0; c < 4; c++) acc[a][b][c] = 0.f;

    for (int kt = 0; kt < NK; kt++) {
        CP_WAIT1();
        __syncthreads();

        // issue next stage FIRST so loads overlap the MMAs below
        const int nxt = kt + STAGES - 1;
        if (nxt < NK)
            issue_stage<K>(A, W, nxt, sb + (nxt % STAGES) * STAGE_BYTES, tid);
        CP_COMMIT();

        const uint32_t stg = sb + (kt % STAGES) * STAGE_BYTES;
        #pragma unroll
        for (int kc = 0; kc < 4; kc++) {
            const int halfk = lane >> 4;
            const int chunk = kc * 2 + halfk;     // 16B chunk 0..7
            const int lrow  = lane & 15;
            // A fragments, 4 M-frags of 16 rows
            uint32_t af[4][4];
            #pragma unroll
            for (int mf = 0; mf < 4; mf++) {
                const int r = wm + mf * 16 + lrow;
                const int sc = chunk ^ (r & 7);
                const uint32_t ad = stg + r * 128 + sc * 16;
                LDSM_X4(af[mf][0], af[mf][1], af[mf][2], af[mf][3], ad + OFF_A);
            }
            // B fragments, 4 N-frags of 8 rows (loaded per 16-row pair)
            #pragma unroll
            for (int p = 0; p < 2; p++) {
                const int r = wn + p * 16 + lrow;
                const int sc = chunk ^ (r & 7);
                const uint32_t bd = stg + r * 128 + sc * 16;
                uint32_t bf[2][2];
                uint32_t t0, t1, t2, t3;
                LDSM_X4(t0, t1, t2, t3, bd + OFF_B);
                bf[0][0] = t0; bf[1][0] = t1; bf[0][1] = t2; bf[1][1] = t3;
                #pragma unroll
                for (int mf = 0; mf < 4; mf++)
                    #pragma unroll
                    for (int q = 0; q < 2; q++)
                        MMA_F16(acc[mf][2 * p + q], af[mf], bf[q]);
            }
        }
    }

    // ---------------- epilogue (register accumulators) ----------------
    #pragma unroll
    for (int nf = 0; nf < 4; nf++) {
        const int col = n0 + wn + nf * 8 + (lane & 3) * 2;
        const float b0 = bias[col], b1 = bias[col + 1];
        #pragma unroll
        for (int mf = 0; mf < 4; mf++) {
            const int r0 = m0 + wm + mf * 16 + (lane >> 2);
            #pragma unroll
            for (int hrow = 0; hrow < 2; hrow++) {
                const size_t row = (size_t)(r0 + hrow * 8);
                float v0 = acc[mf][nf][2 * hrow]     + b0;
                float v1 = acc[mf][nf][2 * hrow + 1] + b1;
                if (EPI == 0 || EPI == 1) {
                    if (EPI == 1) {
                        v0 = v0 / (1.f + __expf(-v0));
                        v1 = v1 / (1.f + __expf(-v1));
                    }
                    __half2 hv = __floats2half2_rn(v0, v1);
                    *(uint32_t*)(Oh + row * N + col) = *(uint32_t*)&hv;
                } else {
                    float2 rr = *(const float2*)(resid + row * N + col);
                    v0 += rr.x; v1 += rr.y;
                    float2 o = {v0, v1};
                    *(float2*)(Cf + row * N + col) = o;
                }
            }
        }
    }
}

// ---------------- decayed scan (3-pass chunked, fp16 p) ----------------------
__device__ __forceinline__ float head_decay(const float* dr_ptr, int h) {
    float dr = dr_ptr[h];
    dr = fminf(fmaxf(dr, 0.9f), 1.0f);
    return powf(dr, 0.125f);
}

__global__ void __launch_bounds__(256) scan_pass1(
    const __half* __restrict__ p, const float* __restrict__ mix_w,
    const float* __restrict__ decay_raw, float* __restrict__ carry)
{
    const int blk = blockIdx.x;
    const int b = blk / NCH, ch = blk % NCH;
    const int t = threadIdx.x;
    const int s0 = ch * CH;
    float cache[4] = {0.f, 0.f, 0.f, 0.f};
    float dly[2], isrow[2];
    #pragma unroll
    for (int j = 0; j < 2; j++) {
        const int h = (2 * (t + j * 256)) >> 7;
        dly[j]   = head_decay(decay_raw, h);
        isrow[j] = (h >= Hh / 2) ? 1.f : 0.f;
    }
    for (int s = s0; s < s0 + CH; s++) {
        const __half2* pr = (const __half2*)(p + ((long)b * Sd + s) * Dd);
        #pragma unroll
        for (int j = 0; j < 2; j++) {
            const int i2 = t + j * 256;
            const int h = (2 * i2) >> 7;
            const float mw = mix_w[h * Sd + s];
            const float c1 = isrow[j] ? mw : 1.f;
            float2 pv = __half22float2(pr[i2]);
            cache[2 * j]     = fmaf(dly[j], cache[2 * j],     pv.x * c1);
            cache[2 * j + 1] = fmaf(dly[j], cache[2 * j + 1], pv.y * c1);
        }
    }
    float* cr = carry + ((long)b * NCH + ch) * Dd;
    #pragma unroll
    for (int j = 0; j < 2; j++) {
        const int f = 2 * (t + j * 256);
        cr[f]     = cache[2 * j];
        cr[f + 1] = cache[2 * j + 1];
    }
}

__global__ void __launch_bounds__(256) scan_pass2(
    const float* __restrict__ decay_raw, float* __restrict__ carry)
{
    const int idx = blockIdx.x * 256 + threadIdx.x;
    const int b = idx >> 10, f = idx & 1023;
    const int h = f >> 7;
    float dr = fminf(fmaxf(decay_raw[h], 0.9f), 1.0f);
    float d2 = dr * dr, d4 = d2 * d2;
    const float dC = d4 * d4;   // dr^8 = decay^CH
    float cin = 0.f;
    for (int ch = 0; ch < NCH; ch++) {
        const long i = ((long)b * NCH + ch) * Dd + f;
        const float e = carry[i];
        carry[i] = cin;
        cin = fmaf(dC, cin, e);
    }
}

__global__ void __launch_bounds__(256) scan_pass3(
    const __half* __restrict__ p, const float* __restrict__ mix_w,
    const float* __restrict__ mix_b, const float* __restrict__ decay_raw,
    const float* __restrict__ carry, __half* __restrict__ mx)
{
    const int blk = blockIdx.x;
    const int b = blk / NCH, ch = blk % NCH;
    const int t = threadIdx.x;
    const int s0 = ch * CH;
    float cache[4], dly[2], isrow[2];
    const float* cr = carry + ((long)b * NCH + ch) * Dd;
    #pragma unroll
    for (int j = 0; j < 2; j++) {
        const int f = 2 * (t + j * 256);
        const int h = f >> 7;
        dly[j]   = head_decay(decay_raw, h);
        isrow[j] = (h >= Hh / 2) ? 1.f : 0.f;
        cache[2 * j]     = cr[f];
        cache[2 * j + 1] = cr[f + 1];
    }
    for (int s = s0; s < s0 + CH; s++) {
        const __half2* pr = (const __half2*)(p + ((long)b * Sd + s) * Dd);
        __half2* mr = (__half2*)(mx + ((long)b * Sd + s) * Dd);
        #pragma unroll
        for (int j = 0; j < 2; j++) {
            const int i2 = t + j * 256;
            const int h = (2 * i2) >> 7;
            const float mw = mix_w[h * Sd + s];
            const float mb = mix_b[h * Sd + s];
            const float c1 = isrow[j] ? mw : 1.f;
            const float c2 = isrow[j] ? 1.f : mw;
            float2 pv = __half22float2(pr[i2]);
            cache[2 * j]     = fmaf(dly[j], cache[2 * j],     pv.x * c1);
            cache[2 * j + 1] = fmaf(dly[j], cache[2 * j + 1], pv.y * c1);
            const float y0 = fmaf(c2, cache[2 * j],     mb);
            const float y1 = fmaf(c2, cache[2 * j + 1], mb);
            mr[i2] = __floats2half2_rn(y0, y1);
        }
    }
}

// ---------------- launcher ----------------------------------------------------
extern "C" void kernel_launch(void* const* d_in, const int* in_sizes, int n_in,
                              void* d_out, int out_size)
{
    const float* x         = (const float*)d_in[0];
    const float* ln1_g     = (const float*)d_in[1];
    const float* ln1_b     = (const float*)d_in[2];
    const float* w1        = (const float*)d_in[3];
    const float* b1        = (const float*)d_in[4];
    const float* w2        = (const float*)d_in[5];
    const float* b2        = (const float*)d_in[6];
    const float* ln2_g     = (const float*)d_in[7];
    const float* ln2_b     = (const float*)d_in[8];
    const float* proj_w    = (const float*)d_in[9];
    const float* proj_b    = (const float*)d_in[10];
    const float* mix_w     = (const float*)d_in[11];
    const float* mix_b     = (const float*)d_in[12];
    const float* decay_raw = (const float*)d_in[13];
    const float* out_w     = (const float*)d_in[14];
    const float* out_b     = (const float*)d_in[15];
    float* out = (float*)d_out;

    __half *hln, *act, *h2, *pb, *mx, *w1h, *w2h, *pwh, *owh;
    float *x2, *carry;
    cudaGetSymbolAddress((void**)&hln,  g_hln);
    cudaGetSymbolAddress((void**)&act,  g_act);
    cudaGetSymbolAddress((void**)&x2,   g_x2);
    cudaGetSymbolAddress((void**)&h2,   g_h2);
    cudaGetSymbolAddress((void**)&pb,   g_p);
    cudaGetSymbolAddress((void**)&mx,   g_mx);
    cudaGetSymbolAddress((void**)&carry, g_carry);
    cudaGetSymbolAddress((void**)&w1h,  g_w1);
    cudaGetSymbolAddress((void**)&w2h,  g_w2);
    cudaGetSymbolAddress((void**)&pwh,  g_pw);
    cudaGetSymbolAddress((void**)&owh,  g_ow);

    cudaFuncSetAttribute((const void*)gemm_tc<Ff, Dd, 1>,
                         cudaFuncAttributeMaxDynamicSharedMemorySize, GEMM_SMEM);
    cudaFuncSetAttribute((const void*)gemm_tc<Dd, Ff, 2>,
                         cudaFuncAttributeMaxDynamicSharedMemorySize, GEMM_SMEM);
    cudaFuncSetAttribute((const void*)gemm_tc<Dd, Dd, 0>,
                         cudaFuncAttributeMaxDynamicSharedMemorySize, GEMM_SMEM);
    cudaFuncSetAttribute((const void*)gemm_tc<Dd, Dd, 2>,
                         cudaFuncAttributeMaxDynamicSharedMemorySize, GEMM_SMEM);

    // 0) weight conversions fp32 -> fp16
    conv_h<<<(Ff * Dd / 4 + 255) / 256, 256>>>(w1, w1h, Ff * Dd / 4);
    conv_h<<<(Dd * Ff / 4 + 255) / 256, 256>>>(w2, w2h, Dd * Ff / 4);
    conv_h<<<(Dd * Dd / 4 + 255) / 256, 256>>>(proj_w, pwh, Dd * Dd / 4);
    conv_h<<<(Dd * Dd / 4 + 255) / 256, 256>>>(out_w, owh, Dd * Dd / 4);

    // 1) LN1 -> fp16 (warp per row)
    ln_f16<<<Mtok / 8, 256>>>(x, ln1_g, ln1_b, hln);
    // 2) act = silu(hln @ w1^T + b1) -> fp16             [16384, 4096]
    gemm_tc<Ff, Dd, 1><<<dim3(Ff / BN, Mtok / BM), NTHR, GEMM_SMEM>>>(
        hln, w1h, b1, nullptr, nullptr, act);
    // 3) x2 = act @ w2^T + b2 + x (fp32)                 [16384, 1024]
    gemm_tc<Dd, Ff, 2><<<dim3(Dd / BN, Mtok / BM), NTHR, GEMM_SMEM>>>(
        act, w2h, b2, x, x2, nullptr);
    // 4) LN2 -> fp16
    ln_f16<<<Mtok / 8, 256>>>(x2, ln2_g, ln2_b, h2);
    // 5) p = h2 @ proj_w^T + proj_b (fp16)               [16384, 1024]
    gemm_tc<Dd, Dd, 0><<<dim3(Dd / BN, Mtok / BM), NTHR, GEMM_SMEM>>>(
        h2, pwh, proj_b, nullptr, nullptr, pb);
    // 6-8) decayed scan over S (fp16 in, fp16 out)
    scan_pass1<<<Bn * NCH, 256>>>(pb, mix_w, decay_raw, carry);
    scan_pass2<<<(Bn * Dd) / 256, 256>>>(decay_raw, carry);
    scan_pass3<<<Bn * NCH, 256>>>(pb, mix_w, mix_b, decay_raw, carry, mx);
    // 9) out = mixed @ out_w^T + out_b + x2 (fp32)       [16384, 1024]
    gemm_tc<Dd, Dd, 2><<<dim3(Dd / BN, Mtok / BM), NTHR, GEMM_SMEM>>>(
        mx, owh, out_b, x2, out, nullptr);
}

// round 12
// speedup vs baseline: 2.8414x; 1.0097x over previous
#include <cuda_runtime.h>
#include <cuda_fp16.h>
#include <math.h>
#include <stdint.h>

// ---------------- problem constants ----------------
#define Bn   4
#define Sd   4096
#define Dd   1024
#define Hh   8
#define Ff   4096          // EXP * D
#define Mtok 16384         // B * S
#define NCH  64            // scan chunks
#define CH   (Sd / NCH)    // 64 steps per chunk

// GEMM tiling: CTA 128x128x64, 8 warps of 64x32, 2 CTAs/SM
#define BM 128
#define BN 128
#define BK 64
#define NTHR 256
#define STAGES 3
#define STAGE_BYTES 32768          // A 16K | B 16K (fp16, 128B rows)
#define OFF_A 0
#define OFF_B 16384
#define GEMM_SMEM (STAGES * STAGE_BYTES)   // 96 KB -> 2 CTAs/SM

// ---------------- small PTX helpers ------------------------------------------
__device__ __forceinline__ uint32_t smem_u32(const void* p) {
    uint32_t a;
    asm("{ .reg .u64 t; cvta.to.shared.u64 t, %1; cvt.u32.u64 %0, t; }"
        : "=r"(a) : "l"(p));
    return a;
}
#define CP_ASYNC16(dst, src) \
    asm volatile("cp.async.cg.shared.global [%0], [%1], 16;" \
        :: "r"(dst), "l"(src) : "memory")
#define CP_COMMIT() asm volatile("cp.async.commit_group;" ::: "memory")
#define CP_WAIT1()  asm volatile("cp.async.wait_group 1;" ::: "memory")

#define LDSM_X4(r0, r1, r2, r3, addr) \
    asm volatile("ldmatrix.sync.aligned.m8n8.x4.shared.b16 {%0,%1,%2,%3}, [%4];" \
        : "=r"(r0), "=r"(r1), "=r"(r2), "=r"(r3) : "r"(addr))

#define MMA_F16(d, a, b) \
    asm volatile("mma.sync.aligned.m16n8k16.row.col.f32.f16.f16.f32 " \
        "{%0,%1,%2,%3}, {%4,%5,%6,%7}, {%8,%9}, {%0,%1,%2,%3};" \
        : "+f"((d)[0]), "+f"((d)[1]), "+f"((d)[2]), "+f"((d)[3]) \
        : "r"((a)[0]), "r"((a)[1]), "r"((a)[2]), "r"((a)[3]), \
          "r"((b)[0]), "r"((b)[1]))

// ---------------- scratch (device globals) ----------------------------------
__device__ __half g_hln [(size_t)Mtok * Dd];
__device__ __half g_act [(size_t)Mtok * Ff];
__device__ __half g_x2  [(size_t)Mtok * Dd];
__device__ __half g_h2  [(size_t)Mtok * Dd];
__device__ __half g_p   [(size_t)Mtok * Dd];
__device__ __half g_mx  [(size_t)Mtok * Dd];
__device__ float  g_carry[(size_t)Bn * NCH * Dd];
__device__ __half g_w1  [(size_t)Ff * Dd];
__device__ __half g_w2  [(size_t)Dd * Ff];
__device__ __half g_pw  [(size_t)Dd * Dd];
__device__ __half g_ow  [(size_t)Dd * Dd];

// ---------------- fused fp32 -> fp16 weight conversion ------------------------
// one grid converts w1 | w2 | proj_w | out_w back-to-back
#define N4_W1 (Ff * Dd / 4)          // 1048576
#define N4_W2 (Dd * Ff / 4)          // 1048576
#define N4_PW (Dd * Dd / 4)          // 262144
#define N4_ALL (N4_W1 + N4_W2 + 2 * N4_PW)

__global__ void __launch_bounds__(256) conv_all(
    const float* __restrict__ w1, const float* __restrict__ w2,
    const float* __restrict__ pw, const float* __restrict__ ow,
    __half* __restrict__ dw1, __half* __restrict__ dw2,
    __half* __restrict__ dpw, __half* __restrict__ dow)
{
    int i = blockIdx.x * 256 + threadIdx.x;
    if (i >= N4_ALL) return;
    const float* src;
    __half* dst;
    int idx = i;
    if (idx < N4_W1)                { src = w1; dst = dw1; }
    else if ((idx -= N4_W1) < N4_W2){ src = w2; dst = dw2; }
    else if ((idx -= N4_W2) < N4_PW){ src = pw; dst = dpw; }
    else { idx -= N4_PW;              src = ow; dst = dow; }
    float4 v = ((const float4*)src)[idx];
    __half2 a = __floats2half2_rn(v.x, v.y);
    __half2 b = __floats2half2_rn(v.z, v.w);
    uint2 o;
    o.x = *(uint32_t*)&a;
    o.y = *(uint32_t*)&b;
    ((uint2*)dst)[idx] = o;
}

// ---------------- LayerNorm -> fp16, warp per row ------------------------------
// FP16SRC: 0 = fp32 input, 1 = fp16 input
template<int FP16SRC>
__global__ void __launch_bounds__(256) ln_f16(
    const void* __restrict__ xin, const float* __restrict__ g,
    const float* __restrict__ bet, __half* __restrict__ o16)
{
    const int wid  = threadIdx.x >> 5;
    const int lane = threadIdx.x & 31;
    const long row = (long)blockIdx.x * 8 + wid;

    float4 v[8];
    if (FP16SRC) {
        const uint2* xr = (const uint2*)((const __half*)xin + row * Dd);
        #pragma unroll
        for (int i = 0; i < 8; i++) {
            uint2 u = xr[lane + i * 32];
            float2 lo = __half22float2(*(__half2*)&u.x);
            float2 hi = __half22float2(*(__half2*)&u.y);
            v[i].x = lo.x; v[i].y = lo.y; v[i].z = hi.x; v[i].w = hi.y;
        }
    } else {
        const float4* xr = (const float4*)((const float*)xin + row * Dd);
        #pragma unroll
        for (int i = 0; i < 8; i++) v[i] = xr[lane + i * 32];
    }

    float s = 0.f, q = 0.f;
    #pragma unroll
    for (int i = 0; i < 8; i++) {
        s += v[i].x + v[i].y + v[i].z + v[i].w;
        q = fmaf(v[i].x, v[i].x, q);
        q = fmaf(v[i].y, v[i].y, q);
        q = fmaf(v[i].z, v[i].z, q);
        q = fmaf(v[i].w, v[i].w, q);
    }
    #pragma unroll
    for (int o = 16; o > 0; o >>= 1) {
        s += __shfl_xor_sync(0xffffffffu, s, o);
        q += __shfl_xor_sync(0xffffffffu, q, o);
    }
    const float mean = s * (1.f / Dd);
    const float var  = q * (1.f / Dd) - mean * mean;
    const float rstd = rsqrtf(var + 1e-5f);

    uint2* outp = (uint2*)(o16 + row * Dd);
    #pragma unroll
    for (int i = 0; i < 8; i++) {
        float4 gg = ((const float4*)g)[lane + i * 32];
        float4 bb = ((const float4*)bet)[lane + i * 32];
        float o0 = (v[i].x - mean) * rstd * gg.x + bb.x;
        float o1 = (v[i].y - mean) * rstd * gg.y + bb.y;
        float o2 = (v[i].z - mean) * rstd * gg.z + bb.z;
        float o3 = (v[i].w - mean) * rstd * gg.w + bb.w;
        __half2 h0 = __floats2half2_rn(o0, o1);
        __half2 h1 = __floats2half2_rn(o2, o3);
        uint2 o;
        o.x = *(uint32_t*)&h0;
        o.y = *(uint32_t*)&h1;
        outp[lane + i * 32] = o;
    }
}

// ---------------- fp16 HMMA GEMM: C = A W^T + epilogue ------------------------
// EPI: 0 = +bias -> fp16
//      1 = silu(+bias) -> fp16
//      2 = +bias + resid(fp16) -> fp32   (final output)
//      3 = +bias + resid(fp32) -> fp16   (x2)
// SMEM rows are 128 B wide (64 fp16); swizzle: chunk c ^= (row & 7)

template<int K>
__device__ __forceinline__ void issue_stage(
    const __half* __restrict__ A, const __half* __restrict__ W,
    int kt, uint32_t stagebase, int tid)
{
    const int kofs = kt * BK;
    #pragma unroll
    for (int j = 0; j < 4; j++) {
        const int i = tid + j * NTHR;         // 0..1023
        const int r = i >> 3;                 // row 0..127
        const int c = i & 7;                  // 16B-chunk 0..7
        const int sc = c ^ (r & 7);           // XOR swizzle (128B rows)
        const uint32_t d = stagebase + r * 128 + sc * 16;
        const size_t go = (size_t)r * K + kofs + c * 8;
        CP_ASYNC16(d + OFF_A, A + go);
        CP_ASYNC16(d + OFF_B, W + go);
    }
}

template<int N, int K, int EPI>
__global__ void __launch_bounds__(NTHR, 2) gemm_tc(
    const __half* __restrict__ Ah, const __half* __restrict__ Wh,
    const float* __restrict__ bias,
    const float* __restrict__ residF, const __half* __restrict__ residH,
    float* __restrict__ Cf, __half* __restrict__ Oh)
{
    extern __shared__ char smem[];
    const uint32_t sb = smem_u32(smem);
    const int tid  = threadIdx.x;
    const int wid  = tid >> 5, lane = tid & 31;
    const int m0   = blockIdx.y * BM;
    const int n0   = blockIdx.x * BN;
    const int wm   = (wid & 1) * 64;      // warp M offset within tile
    const int wn   = (wid >> 1) * 32;     // warp N offset within tile

    const __half* A = Ah + (size_t)m0 * K;
    const __half* W = Wh + (size_t)n0 * K;

    constexpr int NK = K / BK;

    // prologue: fill STAGES-1 stages
    #pragma unroll
    for (int s = 0; s < STAGES - 1; s++) {
        issue_stage<K>(A, W, s, sb + s * STAGE_BYTES, tid);
        CP_COMMIT();
    }

    float acc[4][4][4];
    #pragma unroll
    for (int a = 0; a < 4; a++)
        #pragma unroll
        for (int b = 0; b < 4; b++)
            #pragma unroll
            for (int c = 0; c < 4; c++) acc[a][b][c] = 0.f;

    for (int kt = 0; kt < NK; kt++) {
        CP_WAIT1();
        __syncthreads();

        // issue next stage FIRST so loads overlap the MMAs below
        const int nxt = kt + STAGES - 1;
        if (nxt < NK)
            issue_stage<K>(A, W, nxt, sb + (nxt % STAGES) * STAGE_BYTES, tid);
        CP_COMMIT();

        const uint32_t stg = sb + (kt % STAGES) * STAGE_BYTES;
        #pragma unroll
        for (int kc = 0; kc < 4; kc++) {
            const int halfk = lane >> 4;
            const int chunk = kc * 2 + halfk;     // 16B chunk 0..7
            const int lrow  = lane & 15;
            // A fragments, 4 M-frags of 16 rows
            uint32_t af[4][4];
            #pragma unroll
            for (int mf = 0; mf < 4; mf++) {
                const int r = wm + mf * 16 + lrow;
                const int sc = chunk ^ (r & 7);
                const uint32_t ad = stg + r * 128 + sc * 16;
                LDSM_X4(af[mf][0], af[mf][1], af[mf][2], af[mf][3], ad + OFF_A);
            }
            // B fragments, 4 N-frags of 8 rows (loaded per 16-row pair)
            #pragma unroll
            for (int p = 0; p < 2; p++) {
                const int r = wn + p * 16 + lrow;
                const int sc = chunk ^ (r & 7);
                const uint32_t bd = stg + r * 128 + sc * 16;
                uint32_t bf[2][2];
                uint32_t t0, t1, t2, t3;
                LDSM_X4(t0, t1, t2, t3, bd + OFF_B);
                bf[0][0] = t0; bf[1][0] = t1; bf[0][1] = t2; bf[1][1] = t3;
                #pragma unroll
                for (int mf = 0; mf < 4; mf++)
                    #pragma unroll
                    for (int q = 0; q < 2; q++)
                        MMA_F16(acc[mf][2 * p + q], af[mf], bf[q]);
            }
        }
    }

    // ---------------- epilogue (register accumulators) ----------------
    #pragma unroll
    for (int nf = 0; nf < 4; nf++) {
        const int col = n0 + wn + nf * 8 + (lane & 3) * 2;
        const float b0 = bias[col], b1 = bias[col + 1];
        #pragma unroll
        for (int mf = 0; mf < 4; mf++) {
            const int r0 = m0 + wm + mf * 16 + (lane >> 2);
            #pragma unroll
            for (int hrow = 0; hrow < 2; hrow++) {
                const size_t row = (size_t)(r0 + hrow * 8);
                float v0 = acc[mf][nf][2 * hrow]     + b0;
                float v1 = acc[mf][nf][2 * hrow + 1] + b1;
                if (EPI == 0 || EPI == 1) {
                    if (EPI == 1) {
                        v0 = v0 / (1.f + __expf(-v0));
                        v1 = v1 / (1.f + __expf(-v1));
                    }
                    __half2 hv = __floats2half2_rn(v0, v1);
                    *(uint32_t*)(Oh + row * N + col) = *(uint32_t*)&hv;
                } else if (EPI == 3) {
                    float2 rr = *(const float2*)(residF + row * N + col);
                    v0 += rr.x; v1 += rr.y;
                    __half2 hv = __floats2half2_rn(v0, v1);
                    *(uint32_t*)(Oh + row * N + col) = *(uint32_t*)&hv;
                } else {   // EPI == 2
                    uint32_t ru = *(const uint32_t*)(residH + row * N + col);
                    float2 rr = __half22float2(*(__half2*)&ru);
                    v0 += rr.x; v1 += rr.y;
                    float2 o = {v0, v1};
                    *(float2*)(Cf + row * N + col) = o;
                }
            }
        }
    }
}

// ---------------- decayed scan (3-pass chunked, fp16 p) ----------------------
__device__ __forceinline__ float head_decay(const float* dr_ptr, int h) {
    float dr = dr_ptr[h];
    dr = fminf(fmaxf(dr, 0.9f), 1.0f);
    return powf(dr, 0.125f);
}

__global__ void __launch_bounds__(256) scan_pass1(
    const __half* __restrict__ p, const float* __restrict__ mix_w,
    const float* __restrict__ decay_raw, float* __restrict__ carry)
{
    const int blk = blockIdx.x;
    const int b = blk / NCH, ch = blk % NCH;
    const int t = threadIdx.x;
    const int s0 = ch * CH;
    float cache[4] = {0.f, 0.f, 0.f, 0.f};
    float dly[2], isrow[2];
    #pragma unroll
    for (int j = 0; j < 2; j++) {
        const int h = (2 * (t + j * 256)) >> 7;
        dly[j]   = head_decay(decay_raw, h);
        isrow[j] = (h >= Hh / 2) ? 1.f : 0.f;
    }
    for (int s = s0; s < s0 + CH; s++) {
        const __half2* pr = (const __half2*)(p + ((long)b * Sd + s) * Dd);
        #pragma unroll
        for (int j = 0; j < 2; j++) {
            const int i2 = t + j * 256;
            const int h = (2 * i2) >> 7;
            const float mw = mix_w[h * Sd + s];
            const float c1 = isrow[j] ? mw : 1.f;
            float2 pv = __half22float2(pr[i2]);
            cache[2 * j]     = fmaf(dly[j], cache[2 * j],     pv.x * c1);
            cache[2 * j + 1] = fmaf(dly[j], cache[2 * j + 1], pv.y * c1);
        }
    }
    float* cr = carry + ((long)b * NCH + ch) * Dd;
    #pragma unroll
    for (int j = 0; j < 2; j++) {
        const int f = 2 * (t + j * 256);
        cr[f]     = cache[2 * j];
        cr[f + 1] = cache[2 * j + 1];
    }
}

__global__ void __launch_bounds__(256) scan_pass2(
    const float* __restrict__ decay_raw, float* __restrict__ carry)
{
    const int idx = blockIdx.x * 256 + threadIdx.x;
    const int b = idx >> 10, f = idx & 1023;
    const int h = f >> 7;
    float dr = fminf(fmaxf(decay_raw[h], 0.9f), 1.0f);
    float d2 = dr * dr, d4 = d2 * d2;
    const float dC = d4 * d4;   // dr^8 = decay^CH
    float cin = 0.f;
    for (int ch = 0; ch < NCH; ch++) {
        const long i = ((long)b * NCH + ch) * Dd + f;
        const float e = carry[i];
        carry[i] = cin;
        cin = fmaf(dC, cin, e);
    }
}

__global__ void __launch_bounds__(256) scan_pass3(
    const __half* __restrict__ p, const float* __restrict__ mix_w,
    const float* __restrict__ mix_b, const float* __restrict__ decay_raw,
    const float* __restrict__ carry, __half* __restrict__ mx)
{
    const int blk = blockIdx.x;
    const int b = blk / NCH, ch = blk % NCH;
    const int t = threadIdx.x;
    const int s0 = ch * CH;
    float cache[4], dly[2], isrow[2];
    const float* cr = carry + ((long)b * NCH + ch) * Dd;
    #pragma unroll
    for (int j = 0; j < 2; j++) {
        const int f = 2 * (t + j * 256);
        const int h = f >> 7;
        dly[j]   = head_decay(decay_raw, h);
        isrow[j] = (h >= Hh / 2) ? 1.f : 0.f;
        cache[2 * j]     = cr[f];
        cache[2 * j + 1] = cr[f + 1];
    }
    for (int s = s0; s < s0 + CH; s++) {
        const __half2* pr = (const __half2*)(p + ((long)b * Sd + s) * Dd);
        __half2* mr = (__half2*)(mx + ((long)b * Sd + s) * Dd);
        #pragma unroll
        for (int j = 0; j < 2; j++) {
            const int i2 = t + j * 256;
            const int h = (2 * i2) >> 7;
            const float mw = mix_w[h * Sd + s];
            const float mb = mix_b[h * Sd + s];
            const float c1 = isrow[j] ? mw : 1.f;
            const float c2 = isrow[j] ? 1.f : mw;
            float2 pv = __half22float2(pr[i2]);
            cache[2 * j]     = fmaf(dly[j], cache[2 * j],     pv.x * c1);
            cache[2 * j + 1] = fmaf(dly[j], cache[2 * j + 1], pv.y * c1);
            const float y0 = fmaf(c2, cache[2 * j],     mb);
            const float y1 = fmaf(c2, cache[2 * j + 1], mb);
            mr[i2] = __floats2half2_rn(y0, y1);
        }
    }
}

// ---------------- launcher ----------------------------------------------------
extern "C" void kernel_launch(void* const* d_in, const int* in_sizes, int n_in,
                              void* d_out, int out_size)
{
    const float* x         = (const float*)d_in[0];
    const float* ln1_g     = (const float*)d_in[1];
    const float* ln1_b     = (const float*)d_in[2];
    const float* w1        = (const float*)d_in[3];
    const float* b1        = (const float*)d_in[4];
    const float* w2        = (const float*)d_in[5];
    const float* b2        = (const float*)d_in[6];
    const float* ln2_g     = (const float*)d_in[7];
    const float* ln2_b     = (const float*)d_in[8];
    const float* proj_w    = (const float*)d_in[9];
    const float* proj_b    = (const float*)d_in[10];
    const float* mix_w     = (const float*)d_in[11];
    const float* mix_b     = (const float*)d_in[12];
    const float* decay_raw = (const float*)d_in[13];
    const float* out_w     = (const float*)d_in[14];
    const float* out_b     = (const float*)d_in[15];
    float* out = (float*)d_out;

    __half *hln, *act, *x2, *h2, *pb, *mx, *w1h, *w2h, *pwh, *owh;
    float *carry;
    cudaGetSymbolAddress((void**)&hln,  g_hln);
    cudaGetSymbolAddress((void**)&act,  g_act);
    cudaGetSymbolAddress((void**)&x2,   g_x2);
    cudaGetSymbolAddress((void**)&h2,   g_h2);
    cudaGetSymbolAddress((void**)&pb,   g_p);
    cudaGetSymbolAddress((void**)&mx,   g_mx);
    cudaGetSymbolAddress((void**)&carry, g_carry);
    cudaGetSymbolAddress((void**)&w1h,  g_w1);
    cudaGetSymbolAddress((void**)&w2h,  g_w2);
    cudaGetSymbolAddress((void**)&pwh,  g_pw);
    cudaGetSymbolAddress((void**)&owh,  g_ow);

    cudaFuncSetAttribute((const void*)gemm_tc<Ff, Dd, 1>,
                         cudaFuncAttributeMaxDynamicSharedMemorySize, GEMM_SMEM);
    cudaFuncSetAttribute((const void*)gemm_tc<Dd, Ff, 3>,
                         cudaFuncAttributeMaxDynamicSharedMemorySize, GEMM_SMEM);
    cudaFuncSetAttribute((const void*)gemm_tc<Dd, Dd, 0>,
                         cudaFuncAttributeMaxDynamicSharedMemorySize, GEMM_SMEM);
    cudaFuncSetAttribute((const void*)gemm_tc<Dd, Dd, 2>,
                         cudaFuncAttributeMaxDynamicSharedMemorySize, GEMM_SMEM);

    // 0) fused weight conversions fp32 -> fp16
    conv_all<<<(N4_ALL + 255) / 256, 256>>>(w1, w2, proj_w, out_w,
                                            w1h, w2h, pwh, owh);

    // 1) LN1 -> fp16 (warp per row)
    ln_f16<0><<<Mtok / 8, 256>>>(x, ln1_g, ln1_b, hln);
    // 2) act = silu(hln @ w1^T + b1) -> fp16             [16384, 4096]
    gemm_tc<Ff, Dd, 1><<<dim3(Ff / BN, Mtok / BM), NTHR, GEMM_SMEM>>>(
        hln, w1h, b1, nullptr, nullptr, nullptr, act);
    // 3) x2 = act @ w2^T + b2 + x -> fp16                [16384, 1024]
    gemm_tc<Dd, Ff, 3><<<dim3(Dd / BN, Mtok / BM), NTHR, GEMM_SMEM>>>(
        act, w2h, b2, x, nullptr, nullptr, x2);
    // 4) LN2 (fp16 in) -> fp16
    ln_f16<1><<<Mtok / 8, 256>>>(x2, ln2_g, ln2_b, h2);
    // 5) p = h2 @ proj_w^T + proj_b -> fp16              [16384, 1024]
    gemm_tc<Dd, Dd, 0><<<dim3(Dd / BN, Mtok / BM), NTHR, GEMM_SMEM>>>(
        h2, pwh, proj_b, nullptr, nullptr, nullptr, pb);
    // 6-8) decayed scan over S (fp16 in, fp16 out)
    scan_pass1<<<Bn * NCH, 256>>>(pb, mix_w, decay_raw, carry);
    scan_pass2<<<(Bn * Dd) / 256, 256>>>(decay_raw, carry);
    scan_pass3<<<Bn * NCH, 256>>>(pb, mix_w, mix_b, decay_raw, carry, mx);
    // 9) out = mixed @ out_w^T + out_b + x2 -> fp32      [16384, 1024]
    gemm_tc<Dd, Dd, 2><<<dim3(Dd / BN, Mtok / BM), NTHR, GEMM_SMEM>>>(
        mx, owh, out_b, nullptr, x2, out, nullptr);
}